// round 10
// baseline (speedup 1.0000x reference)
#include <cuda_runtime.h>
#include <cuda_fp16.h>
#include <math.h>
#include <stdint.h>

#define BB   2
#define TT   4096
#define CC   512
#define HH   8
#define DD   64
#define MEMW 256

#define M_TOT (BB*TT)     // 8192
#define QKVN  (3*CC)      // 1536

#define XN  (M_TOT*CC)
#define WAN (QKVN*CC)
#define WPN (CC*CC)

// scratch (allocation-free contract: device globals) — fp16
__device__ __half g_qkv[BB*TT*3*CC];
__device__ __half g_y[BB*TT*CC];
__device__ __half g_xc[XN];
__device__ __half g_wac[WAN];
__device__ __half g_wpc[WPN];

// ===========================================================================
// helpers
// ===========================================================================
__device__ __forceinline__ uint32_t smem_u32(const void* p) {
    uint32_t a;
    asm("{ .reg .u64 t; cvta.to.shared.u64 t, %1; cvt.u32.u64 %0, t; }"
        : "=r"(a) : "l"(p));
    return a;
}
#define SW128(off) ((off) ^ (((off) >> 3) & 0x70))

#define LDSM_X4(r0, r1, r2, r3, addr) \
    asm volatile("ldmatrix.sync.aligned.m8n8.x4.shared.b16 {%0,%1,%2,%3}, [%4];" \
                 : "=r"(r0), "=r"(r1), "=r"(r2), "=r"(r3) : "r"(addr))

#define LDSM_X4T(r0, r1, r2, r3, addr) \
    asm volatile("ldmatrix.sync.aligned.m8n8.x4.trans.shared.b16 {%0,%1,%2,%3}, [%4];" \
                 : "=r"(r0), "=r"(r1), "=r"(r2), "=r"(r3) : "r"(addr))

#define MMA_F16(c, a0, a1, a2, a3, b0, b1) \
    asm volatile("mma.sync.aligned.m16n8k16.row.col.f32.f16.f16.f32 " \
                 "{%0,%1,%2,%3}, {%4,%5,%6,%7}, {%8,%9}, {%0,%1,%2,%3};" \
                 : "+f"((c)[0]), "+f"((c)[1]), "+f"((c)[2]), "+f"((c)[3]) \
                 : "r"(a0), "r"(a1), "r"(a2), "r"(a3), "r"(b0), "r"(b1))

__device__ __forceinline__ void cp_async16(uint32_t s, const void* g) {
    asm volatile("cp.async.cg.shared.global [%0], [%1], 16;"
                 :: "r"(s), "l"(__cvta_generic_to_global(g)));
}
__device__ __forceinline__ void cp_async16_z(uint32_t s, const void* g, int sz) {
    asm volatile("cp.async.cg.shared.global [%0], [%1], 16, %2;"
                 :: "r"(s), "l"(__cvta_generic_to_global(g)), "r"(sz));
}
#define CP_COMMIT() asm volatile("cp.async.commit_group;" ::: "memory")
#define CP_WAIT(n)  asm volatile("cp.async.wait_group %0;" :: "n"(n) : "memory")

__device__ __forceinline__ uint32_t packh2(float a, float b) {
    __half2 h = __floats2half2_rn(a, b);
    return *(uint32_t*)&h;
}

// ===========================================================================
// pre-convert: fp32 -> fp16 for x, w_attn, w_proj
// ===========================================================================
__global__ __launch_bounds__(256) void convert_kernel(const float* __restrict__ x,
                                                      const float* __restrict__ wa,
                                                      const float* __restrict__ wp) {
    const int i8 = blockIdx.x * 256 + threadIdx.x;
    const int total8 = (XN + WAN + WPN) / 8;
    if (i8 >= total8) return;
    const float* src;
    __half* dst;
    int j = i8;
    if (j < XN / 8)                   { src = x;  dst = g_xc; }
    else if ((j -= XN / 8) < WAN / 8) { src = wa; dst = g_wac; }
    else                              { j -= WAN / 8; src = wp; dst = g_wpc; }
    float4 v0 = ((const float4*)src)[j * 2];
    float4 v1 = ((const float4*)src)[j * 2 + 1];
    uint4 o = make_uint4(packh2(v0.x, v0.y), packh2(v0.z, v0.w),
                         packh2(v1.x, v1.y), packh2(v1.z, v1.w));
    ((uint4*)dst)[j] = o;
}

// ===========================================================================
// fp16 mma.sync GEMM (NT) — exact R8 config: CTA 128x128, BK=64, 3-stage.
// ===========================================================================
#define GBM 128
#define GBN 128
#define GBK 64
#define STAGES 3
#define TILE_B (GBM * 128)
#define STAGE_B (2 * TILE_B)
#define GEMM_SMEM (STAGES * STAGE_B)    // 98304

__global__ __launch_bounds__(256) void gemm_fp16(const __half* __restrict__ A,
                                                 const __half* __restrict__ W,
                                                 void* __restrict__ CoutV,
                                                 int M, int N, int K, int round_out) {
    extern __shared__ char dynsm[];
    const uint32_t smb = smem_u32(dynsm);

    const int tid  = threadIdx.x;
    const int lane = tid & 31;
    const int wid  = tid >> 5;
    const int wm   = wid & 3;
    const int wn   = wid >> 2;
    const int m0 = blockIdx.y * GBM;
    const int n0 = blockIdx.x * GBN;

    const int crow = tid >> 3;
    const int cc   = tid & 7;
    const uint32_t cbyte = SW128((uint32_t)(crow * 128 + cc * 16));

    const int nk = K / GBK;

    auto issue_copy = [&](int kt) {
        const int s = kt % STAGES;
        const int k0 = kt * GBK;
        const uint32_t sa = smb + s * STAGE_B;
        const uint32_t sb = sa + TILE_B;
        #pragma unroll
        for (int it = 0; it < 4; it++) {
            const int row = crow + it * 32;
            cp_async16(sa + cbyte + it * 32 * 128,
                       &A[(size_t)(m0 + row) * K + k0 + cc * 8]);
        }
        #pragma unroll
        for (int it = 0; it < 4; it++) {
            const int row = crow + it * 32;
            cp_async16(sb + cbyte + it * 32 * 128,
                       &W[(size_t)(n0 + row) * K + k0 + cc * 8]);
        }
    };

    float acc[2][8][4];
    #pragma unroll
    for (int i = 0; i < 2; i++)
        #pragma unroll
        for (int j = 0; j < 8; j++)
            #pragma unroll
            for (int k = 0; k < 4; k++) acc[i][j][k] = 0.f;

    const int a_row = (lane & 7) + ((lane >> 3) & 1) * 8;
    const int a_col = (lane >> 4) * 16;
    const int b_row = (lane & 7) + (lane >> 4) * 8;
    const int b_col = ((lane >> 3) & 1) * 16;

    #pragma unroll
    for (int s = 0; s < STAGES - 1; s++) {
        issue_copy(s);
        CP_COMMIT();
    }

    for (int kt = 0; kt < nk; kt++) {
        CP_WAIT(STAGES - 2);
        __syncthreads();
        if (kt + STAGES - 1 < nk) issue_copy(kt + STAGES - 1);
        CP_COMMIT();

        const uint32_t sa = smb + (kt % STAGES) * STAGE_B;
        const uint32_t sb = sa + TILE_B;

        #pragma unroll
        for (int ks = 0; ks < 4; ks++) {
            uint32_t a[2][4];
            #pragma unroll
            for (int fm = 0; fm < 2; fm++) {
                int row = wm * 32 + fm * 16 + a_row;
                LDSM_X4(a[fm][0], a[fm][1], a[fm][2], a[fm][3],
                        sa + SW128((uint32_t)(row * 128 + ks * 32 + a_col)));
            }
            uint32_t b[4][4];
            #pragma unroll
            for (int bg = 0; bg < 4; bg++) {
                int row = wn * 64 + bg * 16 + b_row;
                LDSM_X4(b[bg][0], b[bg][1], b[bg][2], b[bg][3],
                        sb + SW128((uint32_t)(row * 128 + ks * 32 + b_col)));
            }
            #pragma unroll
            for (int fm = 0; fm < 2; fm++)
                #pragma unroll
                for (int fn = 0; fn < 8; fn++) {
                    const int bg = fn >> 1;
                    if (fn & 1) {
                        MMA_F16(acc[fm][fn], a[fm][0], a[fm][1], a[fm][2], a[fm][3],
                                b[bg][2], b[bg][3]);
                    } else {
                        MMA_F16(acc[fm][fn], a[fm][0], a[fm][1], a[fm][2], a[fm][3],
                                b[bg][0], b[bg][1]);
                    }
                }
        }
    }
    __syncthreads();

    const int g = lane >> 2;
    const int cpair = (lane & 3) * 2;
    if (round_out) {
        __half* Ch = (__half*)CoutV;
        #pragma unroll
        for (int fm = 0; fm < 2; fm++)
            #pragma unroll
            for (int fn = 0; fn < 8; fn++) {
                int r = m0 + wm * 32 + fm * 16 + g;
                int c = n0 + wn * 64 + fn * 8 + cpair;
                *(uint32_t*)&Ch[(size_t)r * N + c] =
                    packh2(acc[fm][fn][0], acc[fm][fn][1]);
                *(uint32_t*)&Ch[(size_t)(r + 8) * N + c] =
                    packh2(acc[fm][fn][2], acc[fm][fn][3]);
            }
    } else {
        float* Cf = (float*)CoutV;
        #pragma unroll
        for (int fm = 0; fm < 2; fm++)
            #pragma unroll
            for (int fn = 0; fn < 8; fn++) {
                int r = m0 + wm * 32 + fm * 16 + g;
                int c = n0 + wn * 64 + fn * 8 + cpair;
                *(float2*)&Cf[(size_t)r * N + c] =
                    make_float2(acc[fm][fn][0], acc[fm][fn][1]);
                *(float2*)&Cf[(size_t)(r + 8) * N + c] =
                    make_float2(acc[fm][fn][2], acc[fm][fn][3]);
            }
    }
}

// ===========================================================================
// Flash sliding-window attention v3: QT=128, 8 warps x 16 rows, warp-private
// softmax state (no cross-warp exchange), ONE __syncthreads per K-tile.
// ===========================================================================
#define QT 128
#define KT 64
#define NKT 6
#define PPU 36            // P row pitch in u32 (32 used + 4 pad)

// byte offsets
#define AQ   0            // 128*128 = 16384
#define AK   16384        // 2 x 8192
#define AV   32768        // 2 x 8192
#define AP   49152        // 128*36*4 = 18432
#define ATTN_SMEM_BYTES 67584

__global__ __launch_bounds__(256, 2) void attn_flash(const __half* __restrict__ qkv,
                                                     __half* __restrict__ y) {
    extern __shared__ char shm[];
    uint32_t* Pu = (uint32_t*)(shm + AP);

    const int tid  = threadIdx.x;
    const int lane = tid & 31;
    const int wid  = tid >> 5;          // warp owns rows wid*16..+15
    const int q0 = blockIdx.x * QT;
    const int h  = blockIdx.y;
    const int b  = blockIdx.z;
    const int kstart = q0 - MEMW;
    const int kt0 = (q0 < MEMW) ? (MEMW - q0) / KT : 0;

    const __half* qbase = qkv + (size_t)b * TT * QKVN + h * DD;
    const __half* kbase = qbase + CC;
    const __half* vbase = qbase + 2 * CC;

    const uint32_t uQ = smem_u32(shm) + AQ;
    const uint32_t uK = smem_u32(shm) + AK;
    const uint32_t uV = smem_u32(shm) + AV;

    const int a_row = (lane & 7) + ((lane >> 3) & 1) * 8;
    const int a_col = (lane >> 4) * 16;
    const int b_row = (lane & 7) + (lane >> 4) * 8;
    const int b_col = ((lane >> 3) & 1) * 16;
    const int g  = lane >> 2;
    const int c2 = (lane & 3) * 2;
    const int r0 = wid * 16 + g;        // first of this thread's two rows

    // ---- prologue: Q (128 rows) + K/V tile kt0 ----
    #pragma unroll
    for (int it = 0; it < 4; it++) {
        int idx = it * 256 + tid;
        int row = idx >> 3;
        int cc  = idx & 7;
        cp_async16(uQ + SW128((uint32_t)(row * 128 + cc * 16)),
                   &qbase[(size_t)(q0 + row) * QKVN + cc * 8]);
    }
    auto issue_kv = [&](int kt) {
        const uint32_t boff = (kt & 1) * 8192;
        const int kb = kstart + kt * KT;
        #pragma unroll
        for (int it = 0; it < 2; it++) {
            int idx = it * 256 + tid;
            int row = idx >> 3;
            int cc  = idx & 7;
            int gk  = kb + row;
            uint32_t sw = SW128((uint32_t)(row * 128 + cc * 16));
            int ok = (gk >= 0) ? 16 : 0;
            const __half* ks = (gk >= 0) ? &kbase[(size_t)gk * QKVN + cc * 8] : kbase;
            const __half* vs = (gk >= 0) ? &vbase[(size_t)gk * QKVN + cc * 8] : vbase;
            cp_async16_z(uK + boff + sw, ks, ok);
            cp_async16_z(uV + boff + sw, vs, ok);
        }
    };
    issue_kv(kt0);
    CP_COMMIT();

    float m_old0 = -1e30f, m_old1 = -1e30f;
    float srun0 = 0.f, srun1 = 0.f;
    float oacc[8][4];
    #pragma unroll
    for (int i = 0; i < 8; i++)
        #pragma unroll
        for (int j = 0; j < 4; j++) oacc[i][j] = 0.f;

    for (int kt = kt0; kt < NKT; kt++) {
        CP_WAIT(0);
        __syncthreads();               // K/V(kt)+Q visible; prior V readers done
        if (kt + 1 < NKT) { issue_kv(kt + 1); CP_COMMIT(); }

        const int kb = kstart + kt * KT;
        const uint32_t boff = (kt & 1) * 8192;

        // ---- scores: Q(16 rows) x K^T(64 keys), k=64 ----
        float acc[8][4];
        #pragma unroll
        for (int i = 0; i < 8; i++)
            #pragma unroll
            for (int j = 0; j < 4; j++) acc[i][j] = 0.f;

        #pragma unroll
        for (int ks = 0; ks < 4; ks++) {
            uint32_t a[4];
            {
                int row = wid * 16 + a_row;
                LDSM_X4(a[0], a[1], a[2], a[3],
                        uQ + SW128((uint32_t)(row * 128 + ks * 32 + a_col)));
            }
            uint32_t bf[4][4];
            #pragma unroll
            for (int bg = 0; bg < 4; bg++) {
                int row = bg * 16 + b_row;
                LDSM_X4(bf[bg][0], bf[bg][1], bf[bg][2], bf[bg][3],
                        uK + boff + SW128((uint32_t)(row * 128 + ks * 32 + b_col)));
            }
            #pragma unroll
            for (int fn = 0; fn < 8; fn++) {
                const int bg = fn >> 1;
                if (fn & 1) {
                    MMA_F16(acc[fn], a[0], a[1], a[2], a[3], bf[bg][2], bf[bg][3]);
                } else {
                    MMA_F16(acc[fn], a[0], a[1], a[2], a[3], bf[bg][0], bf[bg][1]);
                }
            }
        }

        // ---- mask + scale + row max (warp-internal only) ----
        const int qi0 = q0 + r0;
        const int qi1 = qi0 + 8;
        float mx0 = -1e30f, mx1 = -1e30f;
        #pragma unroll
        for (int fn = 0; fn < 8; fn++) {
            int c  = fn * 8 + c2;
            int kj = kb + c;
            #pragma unroll
            for (int jj = 0; jj < 2; jj++) {
                int k = kj + jj;
                bool ok0 = (k >= 0) && (k <= qi0) && (qi0 - k <= MEMW);
                bool ok1 = (k >= 0) && (k <= qi1) && (qi1 - k <= MEMW);
                acc[fn][jj]     = ok0 ? acc[fn][jj]     * 0.125f : -1e30f;
                acc[fn][2 + jj] = ok1 ? acc[fn][2 + jj] * 0.125f : -1e30f;
                mx0 = fmaxf(mx0, acc[fn][jj]);
                mx1 = fmaxf(mx1, acc[fn][2 + jj]);
            }
        }
        mx0 = fmaxf(mx0, __shfl_xor_sync(0xFFFFFFFF, mx0, 1));
        mx0 = fmaxf(mx0, __shfl_xor_sync(0xFFFFFFFF, mx0, 2));
        mx1 = fmaxf(mx1, __shfl_xor_sync(0xFFFFFFFF, mx1, 1));
        mx1 = fmaxf(mx1, __shfl_xor_sync(0xFFFFFFFF, mx1, 2));

        // ---- online update + exp + P store (warp-private rows) ----
        float m0 = fmaxf(m_old0, mx0);
        float m1 = fmaxf(m_old1, mx1);
        float f0 = __expf(m_old0 - m0);
        float f1 = __expf(m_old1 - m1);
        m_old0 = m0;
        m_old1 = m1;

        float s0 = 0.f, s1 = 0.f;
        #pragma unroll
        for (int fn = 0; fn < 8; fn++) {
            int cu = fn * 4 + (lane & 3);
            float p00 = __expf(acc[fn][0] - m0);
            float p01 = __expf(acc[fn][1] - m0);
            float p10 = __expf(acc[fn][2] - m1);
            float p11 = __expf(acc[fn][3] - m1);
            Pu[r0 * PPU + cu] = packh2(p00, p01);
            Pu[(r0 + 8) * PPU + cu] = packh2(p10, p11);
            s0 += p00 + p01;
            s1 += p10 + p11;
        }
        s0 += __shfl_xor_sync(0xFFFFFFFF, s0, 1);
        s0 += __shfl_xor_sync(0xFFFFFFFF, s0, 2);
        s1 += __shfl_xor_sync(0xFFFFFFFF, s1, 1);
        s1 += __shfl_xor_sync(0xFFFFFFFF, s1, 2);
        srun0 = srun0 * f0 + s0;
        srun1 = srun1 * f1 + s1;

        #pragma unroll
        for (int fn = 0; fn < 8; fn++) {
            oacc[fn][0] *= f0;
            oacc[fn][1] *= f0;
            oacc[fn][2] *= f1;
            oacc[fn][3] *= f1;
        }

        // ---- PV: O(16 x 64d) += P(16 x 64k) x V(64k x 64d) ----
        #pragma unroll
        for (int ks = 0; ks < 4; ks++) {
            uint32_t a[4];
            {
                int base = ks * 8 + (lane & 3);
                a[0] = Pu[r0 * PPU + base];
                a[1] = Pu[(r0 + 8) * PPU + base];
                a[2] = Pu[r0 * PPU + base + 4];
                a[3] = Pu[(r0 + 8) * PPU + base + 4];
            }
            uint32_t bf[4][4];
            #pragma unroll
            for (int g2 = 0; g2 < 4; g2++) {
                int row = ks * 16 + (lane & 7) + ((lane >> 3) & 1) * 8;
                int bcol = g2 * 32 + (lane >> 4) * 16;
                LDSM_X4T(bf[g2][0], bf[g2][1], bf[g2][2], bf[g2][3],
                         uV + boff + SW128((uint32_t)(row * 128 + bcol)));
            }
            #pragma unroll
            for (int fn = 0; fn < 8; fn++) {
                const int bg = fn >> 1;
                if (fn & 1) {
                    MMA_F16(oacc[fn], a[0], a[1], a[2], a[3], bf[bg][2], bf[bg][3]);
                } else {
                    MMA_F16(oacc[fn], a[0], a[1], a[2], a[3], bf[bg][0], bf[bg][1]);
                }
            }
        }
    }

    // ---- epilogue: normalize, fp16 store (cols = full d=64 per warp) ----
    {
        float inv0 = 1.0f / srun0;
        float inv1 = 1.0f / srun1;
        #pragma unroll
        for (int fn = 0; fn < 8; fn++) {
            int col = fn * 8 + c2;
            __half* p0 = &y[(size_t)(b * TT + q0 + r0) * CC + h * DD + col];
            __half* p1 = &y[(size_t)(b * TT + q0 + r0 + 8) * CC + h * DD + col];
            *(uint32_t*)p0 = packh2(oacc[fn][0] * inv0, oacc[fn][1] * inv0);
            *(uint32_t*)p1 = packh2(oacc[fn][2] * inv1, oacc[fn][3] * inv1);
        }
    }
}

// ===========================================================================
extern "C" void kernel_launch(void* const* d_in, const int* in_sizes, int n_in,
                              void* d_out, int out_size) {
    const float* x      = (const float*)d_in[0];
    const float* w_attn = (const float*)d_in[1];
    const float* w_proj = (const float*)d_in[2];
    float* out = (float*)d_out;

    __half *qkv = nullptr, *yb = nullptr, *xc = nullptr, *wac = nullptr, *wpc = nullptr;
    cudaGetSymbolAddress((void**)&qkv, g_qkv);
    cudaGetSymbolAddress((void**)&yb,  g_y);
    cudaGetSymbolAddress((void**)&xc,  g_xc);
    cudaGetSymbolAddress((void**)&wac, g_wac);
    cudaGetSymbolAddress((void**)&wpc, g_wpc);

    cudaFuncSetAttribute(attn_flash,
                         cudaFuncAttributeMaxDynamicSharedMemorySize, ATTN_SMEM_BYTES);
    cudaFuncSetAttribute(gemm_fp16,
                         cudaFuncAttributeMaxDynamicSharedMemorySize, GEMM_SMEM);

    // 0) fp16 pre-convert
    {
        int total8 = (XN + WAN + WPN) / 8;
        convert_kernel<<<(total8 + 255) / 256, 256>>>(x, w_attn, w_proj);
    }
    // 1) QKV projection (fp16 out)
    {
        dim3 grid(QKVN / GBN, M_TOT / GBM);
        gemm_fp16<<<grid, 256, GEMM_SMEM>>>(xc, wac, qkv, M_TOT, QKVN, CC, 1);
    }
    // 2) windowed attention -> y (fp16)
    {
        dim3 grid(TT / QT, HH, BB);
        attn_flash<<<grid, 256, ATTN_SMEM_BYTES>>>(qkv, yb);
    }
    // 3) output projection (fp32 out)
    {
        dim3 grid(CC / GBN, M_TOT / GBM);
        gemm_fp16<<<grid, 256, GEMM_SMEM>>>(yb, wpc, out, M_TOT, CC, CC, 0);
    }
}

// round 11
// speedup vs baseline: 1.0612x; 1.0612x over previous
#include <cuda_runtime.h>
#include <cuda_fp16.h>
#include <math.h>
#include <stdint.h>

#define BB   2
#define TT   4096
#define CC   512
#define HH   8
#define DD   64
#define MEMW 256

#define M_TOT (BB*TT)     // 8192
#define QKVN  (3*CC)      // 1536

#define XN  (M_TOT*CC)
#define WAN (QKVN*CC)
#define WPN (CC*CC)

// scratch (allocation-free contract: device globals) — fp16
__device__ __half g_qkv[BB*TT*3*CC];
__device__ __half g_y[BB*TT*CC];
__device__ __half g_xc[XN];
__device__ __half g_wac[WAN];
__device__ __half g_wpc[WPN];

// ===========================================================================
// helpers
// ===========================================================================
__device__ __forceinline__ uint32_t smem_u32(const void* p) {
    uint32_t a;
    asm("{ .reg .u64 t; cvta.to.shared.u64 t, %1; cvt.u32.u64 %0, t; }"
        : "=r"(a) : "l"(p));
    return a;
}
#define SW128(off) ((off) ^ (((off) >> 3) & 0x70))

#define LDSM_X4(r0, r1, r2, r3, addr) \
    asm volatile("ldmatrix.sync.aligned.m8n8.x4.shared.b16 {%0,%1,%2,%3}, [%4];" \
                 : "=r"(r0), "=r"(r1), "=r"(r2), "=r"(r3) : "r"(addr))

#define LDSM_X4T(r0, r1, r2, r3, addr) \
    asm volatile("ldmatrix.sync.aligned.m8n8.x4.trans.shared.b16 {%0,%1,%2,%3}, [%4];" \
                 : "=r"(r0), "=r"(r1), "=r"(r2), "=r"(r3) : "r"(addr))

#define MMA_F16(c, a0, a1, a2, a3, b0, b1) \
    asm volatile("mma.sync.aligned.m16n8k16.row.col.f32.f16.f16.f32 " \
                 "{%0,%1,%2,%3}, {%4,%5,%6,%7}, {%8,%9}, {%0,%1,%2,%3};" \
                 : "+f"((c)[0]), "+f"((c)[1]), "+f"((c)[2]), "+f"((c)[3]) \
                 : "r"(a0), "r"(a1), "r"(a2), "r"(a3), "r"(b0), "r"(b1))

__device__ __forceinline__ void cp_async16(uint32_t s, const void* g) {
    asm volatile("cp.async.cg.shared.global [%0], [%1], 16;"
                 :: "r"(s), "l"(__cvta_generic_to_global(g)));
}
__device__ __forceinline__ void cp_async16_z(uint32_t s, const void* g, int sz) {
    asm volatile("cp.async.cg.shared.global [%0], [%1], 16, %2;"
                 :: "r"(s), "l"(__cvta_generic_to_global(g)), "r"(sz));
}
#define CP_COMMIT() asm volatile("cp.async.commit_group;" ::: "memory")
#define CP_WAIT(n)  asm volatile("cp.async.wait_group %0;" :: "n"(n) : "memory")

__device__ __forceinline__ uint32_t packh2(float a, float b) {
    __half2 h = __floats2half2_rn(a, b);
    return *(uint32_t*)&h;
}

// ===========================================================================
// pre-convert: fp32 -> fp16 for x, w_attn, w_proj
// ===========================================================================
__global__ __launch_bounds__(256) void convert_kernel(const float* __restrict__ x,
                                                      const float* __restrict__ wa,
                                                      const float* __restrict__ wp) {
    const int i8 = blockIdx.x * 256 + threadIdx.x;
    const int total8 = (XN + WAN + WPN) / 8;
    if (i8 >= total8) return;
    const float* src;
    __half* dst;
    int j = i8;
    if (j < XN / 8)                   { src = x;  dst = g_xc; }
    else if ((j -= XN / 8) < WAN / 8) { src = wa; dst = g_wac; }
    else                              { j -= WAN / 8; src = wp; dst = g_wpc; }
    float4 v0 = ((const float4*)src)[j * 2];
    float4 v1 = ((const float4*)src)[j * 2 + 1];
    uint4 o = make_uint4(packh2(v0.x, v0.y), packh2(v0.z, v0.w),
                         packh2(v1.x, v1.y), packh2(v1.z, v1.w));
    ((uint4*)dst)[j] = o;
}

// ===========================================================================
// fp16 mma.sync GEMM (NT) — exact R8 config + mbase row offset.
// CTA 128x128, BK=64, 3-stage cp.async, 8 warps (4m x 2n).
// ===========================================================================
#define GBM 128
#define GBN 128
#define GBK 64
#define STAGES 3
#define TILE_B (GBM * 128)
#define STAGE_B (2 * TILE_B)
#define GEMM_SMEM (STAGES * STAGE_B)    // 98304

__global__ __launch_bounds__(256) void gemm_fp16(const __half* __restrict__ A,
                                                 const __half* __restrict__ W,
                                                 void* __restrict__ CoutV,
                                                 int M, int N, int K,
                                                 int round_out, int mbase) {
    extern __shared__ char dynsm[];
    const uint32_t smb = smem_u32(dynsm);

    const int tid  = threadIdx.x;
    const int lane = tid & 31;
    const int wid  = tid >> 5;
    const int wm   = wid & 3;
    const int wn   = wid >> 2;
    const int m0 = mbase + blockIdx.y * GBM;
    const int n0 = blockIdx.x * GBN;

    const int crow = tid >> 3;
    const int cc   = tid & 7;
    const uint32_t cbyte = SW128((uint32_t)(crow * 128 + cc * 16));

    const int nk = K / GBK;

    auto issue_copy = [&](int kt) {
        const int s = kt % STAGES;
        const int k0 = kt * GBK;
        const uint32_t sa = smb + s * STAGE_B;
        const uint32_t sb = sa + TILE_B;
        #pragma unroll
        for (int it = 0; it < 4; it++) {
            const int row = crow + it * 32;
            cp_async16(sa + cbyte + it * 32 * 128,
                       &A[(size_t)(m0 + row) * K + k0 + cc * 8]);
        }
        #pragma unroll
        for (int it = 0; it < 4; it++) {
            const int row = crow + it * 32;
            cp_async16(sb + cbyte + it * 32 * 128,
                       &W[(size_t)(n0 + row) * K + k0 + cc * 8]);
        }
    };

    float acc[2][8][4];
    #pragma unroll
    for (int i = 0; i < 2; i++)
        #pragma unroll
        for (int j = 0; j < 8; j++)
            #pragma unroll
            for (int k = 0; k < 4; k++) acc[i][j][k] = 0.f;

    const int a_row = (lane & 7) + ((lane >> 3) & 1) * 8;
    const int a_col = (lane >> 4) * 16;
    const int b_row = (lane & 7) + (lane >> 4) * 8;
    const int b_col = ((lane >> 3) & 1) * 16;

    #pragma unroll
    for (int s = 0; s < STAGES - 1; s++) {
        issue_copy(s);
        CP_COMMIT();
    }

    for (int kt = 0; kt < nk; kt++) {
        CP_WAIT(STAGES - 2);
        __syncthreads();
        if (kt + STAGES - 1 < nk) issue_copy(kt + STAGES - 1);
        CP_COMMIT();

        const uint32_t sa = smb + (kt % STAGES) * STAGE_B;
        const uint32_t sb = sa + TILE_B;

        #pragma unroll
        for (int ks = 0; ks < 4; ks++) {
            uint32_t a[2][4];
            #pragma unroll
            for (int fm = 0; fm < 2; fm++) {
                int row = wm * 32 + fm * 16 + a_row;
                LDSM_X4(a[fm][0], a[fm][1], a[fm][2], a[fm][3],
                        sa + SW128((uint32_t)(row * 128 + ks * 32 + a_col)));
            }
            uint32_t b[4][4];
            #pragma unroll
            for (int bg = 0; bg < 4; bg++) {
                int row = wn * 64 + bg * 16 + b_row;
                LDSM_X4(b[bg][0], b[bg][1], b[bg][2], b[bg][3],
                        sb + SW128((uint32_t)(row * 128 + ks * 32 + b_col)));
            }
            #pragma unroll
            for (int fm = 0; fm < 2; fm++)
                #pragma unroll
                for (int fn = 0; fn < 8; fn++) {
                    const int bg = fn >> 1;
                    if (fn & 1) {
                        MMA_F16(acc[fm][fn], a[fm][0], a[fm][1], a[fm][2], a[fm][3],
                                b[bg][2], b[bg][3]);
                    } else {
                        MMA_F16(acc[fm][fn], a[fm][0], a[fm][1], a[fm][2], a[fm][3],
                                b[bg][0], b[bg][1]);
                    }
                }
        }
    }
    __syncthreads();

    const int g = lane >> 2;
    const int cpair = (lane & 3) * 2;
    if (round_out) {
        __half* Ch = (__half*)CoutV;
        #pragma unroll
        for (int fm = 0; fm < 2; fm++)
            #pragma unroll
            for (int fn = 0; fn < 8; fn++) {
                int r = m0 + wm * 32 + fm * 16 + g;
                int c = n0 + wn * 64 + fn * 8 + cpair;
                *(uint32_t*)&Ch[(size_t)r * N + c] =
                    packh2(acc[fm][fn][0], acc[fm][fn][1]);
                *(uint32_t*)&Ch[(size_t)(r + 8) * N + c] =
                    packh2(acc[fm][fn][2], acc[fm][fn][3]);
            }
    } else {
        float* Cf = (float*)CoutV;
        #pragma unroll
        for (int fm = 0; fm < 2; fm++)
            #pragma unroll
            for (int fn = 0; fn < 8; fn++) {
                int r = m0 + wm * 32 + fm * 16 + g;
                int c = n0 + wn * 64 + fn * 8 + cpair;
                *(float2*)&Cf[(size_t)r * N + c] =
                    make_float2(acc[fm][fn][0], acc[fm][fn][1]);
                *(float2*)&Cf[(size_t)(r + 8) * N + c] =
                    make_float2(acc[fm][fn][2], acc[fm][fn][3]);
            }
    }
}

// ===========================================================================
// Flash sliding-window attention — exact R8 version, batch passed as param.
// ===========================================================================
#define QT 64
#define KT 64
#define NKT 5
#define PPU 36

#define AQ   0
#define AK   8192
#define AV   24576
#define AP   40960
#define APM  50176
#define APS  50688
#define ATTN_SMEM_BYTES 51200

__global__ __launch_bounds__(256, 2) void attn_flash(const __half* __restrict__ qkv,
                                                     __half* __restrict__ y,
                                                     int bfix) {
    extern __shared__ char shm[];
    float* pmax = (float*)(shm + APM);
    float* psum = (float*)(shm + APS);
    uint32_t* Pu = (uint32_t*)(shm + AP);

    const int tid  = threadIdx.x;
    const int lane = tid & 31;
    const int wid  = tid >> 5;
    const int wm   = wid & 3;
    const int wn   = wid >> 2;
    const int q0 = blockIdx.x * QT;
    const int h  = blockIdx.y;
    const int b  = bfix;
    const int kstart = q0 - MEMW;
    const int kt0 = (q0 < MEMW) ? (MEMW - q0) / KT : 0;

    const __half* qbase = qkv + (size_t)b * TT * QKVN + h * DD;
    const __half* kbase = qbase + CC;
    const __half* vbase = qbase + 2 * CC;

    const uint32_t uQ = smem_u32(shm) + AQ;
    const uint32_t uK = smem_u32(shm) + AK;
    const uint32_t uV = smem_u32(shm) + AV;

    const int a_row = (lane & 7) + ((lane >> 3) & 1) * 8;
    const int a_col = (lane >> 4) * 16;
    const int b_row = (lane & 7) + (lane >> 4) * 8;
    const int b_col = ((lane >> 3) & 1) * 16;
    const int g  = lane >> 2;
    const int c2 = (lane & 3) * 2;
    const int r0 = wm * 16 + g;

    #pragma unroll
    for (int it = 0; it < 2; it++) {
        int idx = it * 256 + tid;
        int row = idx >> 3;
        int cc  = idx & 7;
        cp_async16(uQ + SW128((uint32_t)(row * 128 + cc * 16)),
                   &qbase[(size_t)(q0 + row) * QKVN + cc * 8]);
    }
    auto issue_kv = [&](int kt) {
        const uint32_t boff = (kt & 1) * 8192;
        const int kb = kstart + kt * KT;
        #pragma unroll
        for (int it = 0; it < 2; it++) {
            int idx = it * 256 + tid;
            int row = idx >> 3;
            int cc  = idx & 7;
            int gk  = kb + row;
            uint32_t sw = SW128((uint32_t)(row * 128 + cc * 16));
            int ok = (gk >= 0) ? 16 : 0;
            const __half* ks = (gk >= 0) ? &kbase[(size_t)gk * QKVN + cc * 8] : kbase;
            const __half* vs = (gk >= 0) ? &vbase[(size_t)gk * QKVN + cc * 8] : vbase;
            cp_async16_z(uK + boff + sw, ks, ok);
            cp_async16_z(uV + boff + sw, vs, ok);
        }
    };
    issue_kv(kt0);
    CP_COMMIT();

    float m_old0 = -1e30f, m_old1 = -1e30f;
    float srun0 = 0.f, srun1 = 0.f;
    float oacc[4][4];
    #pragma unroll
    for (int i = 0; i < 4; i++)
        #pragma unroll
        for (int j = 0; j < 4; j++) oacc[i][j] = 0.f;

    for (int kt = kt0; kt < NKT; kt++) {
        CP_WAIT(0);
        __syncthreads();
        if (kt + 1 < NKT) { issue_kv(kt + 1); CP_COMMIT(); }

        const int kb = kstart + kt * KT;
        const uint32_t boff = (kt & 1) * 8192;

        float acc[4][4];
        #pragma unroll
        for (int i = 0; i < 4; i++)
            #pragma unroll
            for (int j = 0; j < 4; j++) acc[i][j] = 0.f;

        #pragma unroll
        for (int ks = 0; ks < 4; ks++) {
            uint32_t a[4];
            {
                int row = wm * 16 + a_row;
                LDSM_X4(a[0], a[1], a[2], a[3],
                        uQ + SW128((uint32_t)(row * 128 + ks * 32 + a_col)));
            }
            uint32_t bf[2][4];
            #pragma unroll
            for (int g2 = 0; g2 < 2; g2++) {
                int row = wn * 32 + g2 * 16 + b_row;
                LDSM_X4(bf[g2][0], bf[g2][1], bf[g2][2], bf[g2][3],
                        uK + boff + SW128((uint32_t)(row * 128 + ks * 32 + b_col)));
            }
            #pragma unroll
            for (int fn = 0; fn < 4; fn++) {
                const int bg = fn >> 1;
                if (fn & 1) {
                    MMA_F16(acc[fn], a[0], a[1], a[2], a[3], bf[bg][2], bf[bg][3]);
                } else {
                    MMA_F16(acc[fn], a[0], a[1], a[2], a[3], bf[bg][0], bf[bg][1]);
                }
            }
        }

        const int qi0 = q0 + r0;
        const int qi1 = qi0 + 8;
        float mx0 = -1e30f, mx1 = -1e30f;
        #pragma unroll
        for (int fn = 0; fn < 4; fn++) {
            int c  = wn * 32 + fn * 8 + c2;
            int kj = kb + c;
            #pragma unroll
            for (int jj = 0; jj < 2; jj++) {
                int k = kj + jj;
                bool ok0 = (k >= 0) && (k <= qi0) && (qi0 - k <= MEMW);
                bool ok1 = (k >= 0) && (k <= qi1) && (qi1 - k <= MEMW);
                acc[fn][jj]     = ok0 ? acc[fn][jj]     * 0.125f : -1e30f;
                acc[fn][2 + jj] = ok1 ? acc[fn][2 + jj] * 0.125f : -1e30f;
                mx0 = fmaxf(mx0, acc[fn][jj]);
                mx1 = fmaxf(mx1, acc[fn][2 + jj]);
            }
        }
        mx0 = fmaxf(mx0, __shfl_xor_sync(0xFFFFFFFF, mx0, 1));
        mx0 = fmaxf(mx0, __shfl_xor_sync(0xFFFFFFFF, mx0, 2));
        mx1 = fmaxf(mx1, __shfl_xor_sync(0xFFFFFFFF, mx1, 1));
        mx1 = fmaxf(mx1, __shfl_xor_sync(0xFFFFFFFF, mx1, 2));
        if ((lane & 3) == 0) {
            pmax[r0 * 2 + wn] = mx0;
            pmax[(r0 + 8) * 2 + wn] = mx1;
        }
        __syncthreads();

        float m0 = fmaxf(m_old0, fmaxf(pmax[r0 * 2], pmax[r0 * 2 + 1]));
        float m1 = fmaxf(m_old1, fmaxf(pmax[(r0 + 8) * 2], pmax[(r0 + 8) * 2 + 1]));
        float f0 = __expf(m_old0 - m0);
        float f1 = __expf(m_old1 - m1);
        m_old0 = m0;
        m_old1 = m1;

        float s0 = 0.f, s1 = 0.f;
        #pragma unroll
        for (int fn = 0; fn < 4; fn++) {
            int cu = wn * 16 + fn * 4 + (lane & 3);
            float p00 = __expf(acc[fn][0] - m0);
            float p01 = __expf(acc[fn][1] - m0);
            float p10 = __expf(acc[fn][2] - m1);
            float p11 = __expf(acc[fn][3] - m1);
            Pu[r0 * PPU + cu] = packh2(p00, p01);
            Pu[(r0 + 8) * PPU + cu] = packh2(p10, p11);
            s0 += p00 + p01;
            s1 += p10 + p11;
        }
        s0 += __shfl_xor_sync(0xFFFFFFFF, s0, 1);
        s0 += __shfl_xor_sync(0xFFFFFFFF, s0, 2);
        s1 += __shfl_xor_sync(0xFFFFFFFF, s1, 1);
        s1 += __shfl_xor_sync(0xFFFFFFFF, s1, 2);
        if ((lane & 3) == 0) {
            psum[r0 * 2 + wn] = s0;
            psum[(r0 + 8) * 2 + wn] = s1;
        }
        #pragma unroll
        for (int fn = 0; fn < 4; fn++) {
            oacc[fn][0] *= f0;
            oacc[fn][1] *= f0;
            oacc[fn][2] *= f1;
            oacc[fn][3] *= f1;
        }
        __syncthreads();

        srun0 = srun0 * f0 + psum[r0 * 2] + psum[r0 * 2 + 1];
        srun1 = srun1 * f1 + psum[(r0 + 8) * 2] + psum[(r0 + 8) * 2 + 1];

        #pragma unroll
        for (int ks = 0; ks < 4; ks++) {
            uint32_t a[4];
            {
                int base = ks * 8 + (lane & 3);
                a[0] = Pu[r0 * PPU + base];
                a[1] = Pu[(r0 + 8) * PPU + base];
                a[2] = Pu[r0 * PPU + base + 4];
                a[3] = Pu[(r0 + 8) * PPU + base + 4];
            }
            uint32_t bf[2][4];
            #pragma unroll
            for (int g2 = 0; g2 < 2; g2++) {
                int row = ks * 16 + (lane & 7) + ((lane >> 3) & 1) * 8;
                int bcol = wn * 64 + g2 * 32 + (lane >> 4) * 16;
                LDSM_X4T(bf[g2][0], bf[g2][1], bf[g2][2], bf[g2][3],
                         uV + boff + SW128((uint32_t)(row * 128 + bcol)));
            }
            #pragma unroll
            for (int fn = 0; fn < 4; fn++) {
                const int bg = fn >> 1;
                if (fn & 1) {
                    MMA_F16(oacc[fn], a[0], a[1], a[2], a[3], bf[bg][2], bf[bg][3]);
                } else {
                    MMA_F16(oacc[fn], a[0], a[1], a[2], a[3], bf[bg][0], bf[bg][1]);
                }
            }
        }
    }

    {
        float inv0 = 1.0f / srun0;
        float inv1 = 1.0f / srun1;
        #pragma unroll
        for (int fn = 0; fn < 4; fn++) {
            int col = wn * 32 + fn * 8 + c2;
            __half* p0 = &y[(size_t)(b * TT + q0 + r0) * CC + h * DD + col];
            __half* p1 = &y[(size_t)(b * TT + q0 + r0 + 8) * CC + h * DD + col];
            *(uint32_t*)p0 = packh2(oacc[fn][0] * inv0, oacc[fn][1] * inv0);
            *(uint32_t*)p1 = packh2(oacc[fn][2] * inv1, oacc[fn][3] * inv1);
        }
    }
}

// ===========================================================================
// launcher: 2-stream batch pipeline inside the captured graph.
//   s0: convert -> QKV(b0) -> attn(b0) -> proj(b0)
//   s1:            (after QKV(b0)) QKV(b1) -> attn(b1) -> proj(b1)
// join back to s0 before return.
// ===========================================================================
extern "C" void kernel_launch(void* const* d_in, const int* in_sizes, int n_in,
                              void* d_out, int out_size) {
    const float* x      = (const float*)d_in[0];
    const float* w_attn = (const float*)d_in[1];
    const float* w_proj = (const float*)d_in[2];
    float* out = (float*)d_out;

    __half *qkv = nullptr, *yb = nullptr, *xc = nullptr, *wac = nullptr, *wpc = nullptr;
    cudaGetSymbolAddress((void**)&qkv, g_qkv);
    cudaGetSymbolAddress((void**)&yb,  g_y);
    cudaGetSymbolAddress((void**)&xc,  g_xc);
    cudaGetSymbolAddress((void**)&wac, g_wac);
    cudaGetSymbolAddress((void**)&wpc, g_wpc);

    cudaFuncSetAttribute(attn_flash,
                         cudaFuncAttributeMaxDynamicSharedMemorySize, ATTN_SMEM_BYTES);
    cudaFuncSetAttribute(gemm_fp16,
                         cudaFuncAttributeMaxDynamicSharedMemorySize, GEMM_SMEM);

    // side stream + events (created per call; host-side only, not device mem;
    // intentionally not destroyed so capture retains valid handles)
    cudaStream_t s1;
    cudaStreamCreateWithFlags(&s1, cudaStreamNonBlocking);
    cudaEvent_t evQ0, evJoin;
    cudaEventCreateWithFlags(&evQ0,  cudaEventDisableTiming);
    cudaEventCreateWithFlags(&evJoin, cudaEventDisableTiming);

    const int MH = M_TOT / 2;   // 4096 rows per batch

    // 0) fp16 pre-convert (legacy stream)
    {
        int total8 = (XN + WAN + WPN) / 8;
        convert_kernel<<<(total8 + 255) / 256, 256, 0, 0>>>(x, w_attn, w_proj);
    }
    // 1a) QKV(b0) on legacy stream
    {
        dim3 grid(QKVN / GBN, MH / GBM);
        gemm_fp16<<<grid, 256, GEMM_SMEM, 0>>>(xc, wac, qkv, M_TOT, QKVN, CC, 1, 0);
    }
    // fork: s1 starts after QKV(b0)
    cudaEventRecord(evQ0, 0);
    cudaStreamWaitEvent(s1, evQ0, 0);

    // 1b) QKV(b1) on s1
    {
        dim3 grid(QKVN / GBN, MH / GBM);
        gemm_fp16<<<grid, 256, GEMM_SMEM, s1>>>(xc, wac, qkv, M_TOT, QKVN, CC, 1, MH);
    }
    // 2a) attn(b0) + 3a) proj(b0) on legacy stream (overlap QKV(b1))
    {
        dim3 grid(TT / QT, HH);
        attn_flash<<<grid, 256, ATTN_SMEM_BYTES, 0>>>(qkv, yb, 0);
    }
    {
        dim3 grid(CC / GBN, MH / GBM);
        gemm_fp16<<<grid, 256, GEMM_SMEM, 0>>>(yb, wpc, out, M_TOT, CC, CC, 0, 0);
    }
    // 2b) attn(b1) + 3b) proj(b1) on s1
    {
        dim3 grid(TT / QT, HH);
        attn_flash<<<grid, 256, ATTN_SMEM_BYTES, s1>>>(qkv, yb, 1);
    }
    {
        dim3 grid(CC / GBN, MH / GBM);
        gemm_fp16<<<grid, 256, GEMM_SMEM, s1>>>(yb, wpc, out, M_TOT, CC, CC, 0, MH);
    }

    // join: legacy stream waits for s1 pipeline
    cudaEventRecord(evJoin, s1);
    cudaStreamWaitEvent(0, evJoin, 0);
}

// round 12
// speedup vs baseline: 1.0657x; 1.0042x over previous
#include <cuda_runtime.h>
#include <cuda_fp16.h>
#include <math.h>
#include <stdint.h>

#define BB   2
#define TT   4096
#define CC   512
#define HH   8
#define DD   64
#define MEMW 256

#define M_TOT (BB*TT)     // 8192
#define QKVN  (3*CC)      // 1536

#define XN  (M_TOT*CC)
#define WAN (QKVN*CC)
#define WPN (CC*CC)

// scratch (allocation-free contract: device globals) — fp16
__device__ __half g_qkv[BB*TT*3*CC];
__device__ __half g_y[BB*TT*CC];
__device__ __half g_xc[XN];
__device__ __half g_wac[WAN];
__device__ __half g_wpc[WPN];

// ===========================================================================
// helpers
// ===========================================================================
__device__ __forceinline__ uint32_t smem_u32(const void* p) {
    uint32_t a;
    asm("{ .reg .u64 t; cvta.to.shared.u64 t, %1; cvt.u32.u64 %0, t; }"
        : "=r"(a) : "l"(p));
    return a;
}
#define SW128(off) ((off) ^ (((off) >> 3) & 0x70))

#define LDSM_X4(r0, r1, r2, r3, addr) \
    asm volatile("ldmatrix.sync.aligned.m8n8.x4.shared.b16 {%0,%1,%2,%3}, [%4];" \
                 : "=r"(r0), "=r"(r1), "=r"(r2), "=r"(r3) : "r"(addr))

#define LDSM_X4T(r0, r1, r2, r3, addr) \
    asm volatile("ldmatrix.sync.aligned.m8n8.x4.trans.shared.b16 {%0,%1,%2,%3}, [%4];" \
                 : "=r"(r0), "=r"(r1), "=r"(r2), "=r"(r3) : "r"(addr))

#define MMA_F16(c, a0, a1, a2, a3, b0, b1) \
    asm volatile("mma.sync.aligned.m16n8k16.row.col.f32.f16.f16.f32 " \
                 "{%0,%1,%2,%3}, {%4,%5,%6,%7}, {%8,%9}, {%0,%1,%2,%3};" \
                 : "+f"((c)[0]), "+f"((c)[1]), "+f"((c)[2]), "+f"((c)[3]) \
                 : "r"(a0), "r"(a1), "r"(a2), "r"(a3), "r"(b0), "r"(b1))

__device__ __forceinline__ void cp_async16(uint32_t s, const void* g) {
    asm volatile("cp.async.cg.shared.global [%0], [%1], 16;"
                 :: "r"(s), "l"(__cvta_generic_to_global(g)));
}
__device__ __forceinline__ void cp_async16_z(uint32_t s, const void* g, int sz) {
    asm volatile("cp.async.cg.shared.global [%0], [%1], 16, %2;"
                 :: "r"(s), "l"(__cvta_generic_to_global(g)), "r"(sz));
}
#define CP_COMMIT() asm volatile("cp.async.commit_group;" ::: "memory")
#define CP_WAIT(n)  asm volatile("cp.async.wait_group %0;" :: "n"(n) : "memory")

__device__ __forceinline__ uint32_t packh2(float a, float b) {
    __half2 h = __floats2half2_rn(a, b);
    return *(uint32_t*)&h;
}
__device__ __forceinline__ float ex2f(float x) {
    float r;
    asm("ex2.approx.f32 %0, %1;" : "=f"(r) : "f"(x));
    return r;
}

// scores pre-scaled by 1/sqrt(d) * log2(e) so softmax uses raw ex2
#define SCL 0.18033688011112042f     // 0.125 * 1.4426950408889634

// ===========================================================================
// pre-convert: fp32 -> fp16 for x, w_attn, w_proj
// ===========================================================================
__global__ __launch_bounds__(256) void convert_kernel(const float* __restrict__ x,
                                                      const float* __restrict__ wa,
                                                      const float* __restrict__ wp) {
    const int i8 = blockIdx.x * 256 + threadIdx.x;
    const int total8 = (XN + WAN + WPN) / 8;
    if (i8 >= total8) return;
    const float* src;
    __half* dst;
    int j = i8;
    if (j < XN / 8)                   { src = x;  dst = g_xc; }
    else if ((j -= XN / 8) < WAN / 8) { src = wa; dst = g_wac; }
    else                              { j -= WAN / 8; src = wp; dst = g_wpc; }
    float4 v0 = ((const float4*)src)[j * 2];
    float4 v1 = ((const float4*)src)[j * 2 + 1];
    uint4 o = make_uint4(packh2(v0.x, v0.y), packh2(v0.z, v0.w),
                         packh2(v1.x, v1.y), packh2(v1.z, v1.w));
    ((uint4*)dst)[j] = o;
}

// ===========================================================================
// fp16 mma.sync GEMM (NT) — R8 config + mbase row offset (unchanged R11)
// ===========================================================================
#define GBM 128
#define GBN 128
#define GBK 64
#define STAGES 3
#define TILE_B (GBM * 128)
#define STAGE_B (2 * TILE_B)
#define GEMM_SMEM (STAGES * STAGE_B)    // 98304

__global__ __launch_bounds__(256) void gemm_fp16(const __half* __restrict__ A,
                                                 const __half* __restrict__ W,
                                                 void* __restrict__ CoutV,
                                                 int M, int N, int K,
                                                 int round_out, int mbase) {
    extern __shared__ char dynsm[];
    const uint32_t smb = smem_u32(dynsm);

    const int tid  = threadIdx.x;
    const int lane = tid & 31;
    const int wid  = tid >> 5;
    const int wm   = wid & 3;
    const int wn   = wid >> 2;
    const int m0 = mbase + blockIdx.y * GBM;
    const int n0 = blockIdx.x * GBN;

    const int crow = tid >> 3;
    const int cc   = tid & 7;
    const uint32_t cbyte = SW128((uint32_t)(crow * 128 + cc * 16));

    const int nk = K / GBK;

    auto issue_copy = [&](int kt) {
        const int s = kt % STAGES;
        const int k0 = kt * GBK;
        const uint32_t sa = smb + s * STAGE_B;
        const uint32_t sb = sa + TILE_B;
        #pragma unroll
        for (int it = 0; it < 4; it++) {
            const int row = crow + it * 32;
            cp_async16(sa + cbyte + it * 32 * 128,
                       &A[(size_t)(m0 + row) * K + k0 + cc * 8]);
        }
        #pragma unroll
        for (int it = 0; it < 4; it++) {
            const int row = crow + it * 32;
            cp_async16(sb + cbyte + it * 32 * 128,
                       &W[(size_t)(n0 + row) * K + k0 + cc * 8]);
        }
    };

    float acc[2][8][4];
    #pragma unroll
    for (int i = 0; i < 2; i++)
        #pragma unroll
        for (int j = 0; j < 8; j++)
            #pragma unroll
            for (int k = 0; k < 4; k++) acc[i][j][k] = 0.f;

    const int a_row = (lane & 7) + ((lane >> 3) & 1) * 8;
    const int a_col = (lane >> 4) * 16;
    const int b_row = (lane & 7) + (lane >> 4) * 8;
    const int b_col = ((lane >> 3) & 1) * 16;

    #pragma unroll
    for (int s = 0; s < STAGES - 1; s++) {
        issue_copy(s);
        CP_COMMIT();
    }

    for (int kt = 0; kt < nk; kt++) {
        CP_WAIT(STAGES - 2);
        __syncthreads();
        if (kt + STAGES - 1 < nk) issue_copy(kt + STAGES - 1);
        CP_COMMIT();

        const uint32_t sa = smb + (kt % STAGES) * STAGE_B;
        const uint32_t sb = sa + TILE_B;

        #pragma unroll
        for (int ks = 0; ks < 4; ks++) {
            uint32_t a[2][4];
            #pragma unroll
            for (int fm = 0; fm < 2; fm++) {
                int row = wm * 32 + fm * 16 + a_row;
                LDSM_X4(a[fm][0], a[fm][1], a[fm][2], a[fm][3],
                        sa + SW128((uint32_t)(row * 128 + ks * 32 + a_col)));
            }
            uint32_t b[4][4];
            #pragma unroll
            for (int bg = 0; bg < 4; bg++) {
                int row = wn * 64 + bg * 16 + b_row;
                LDSM_X4(b[bg][0], b[bg][1], b[bg][2], b[bg][3],
                        sb + SW128((uint32_t)(row * 128 + ks * 32 + b_col)));
            }
            #pragma unroll
            for (int fm = 0; fm < 2; fm++)
                #pragma unroll
                for (int fn = 0; fn < 8; fn++) {
                    const int bg = fn >> 1;
                    if (fn & 1) {
                        MMA_F16(acc[fm][fn], a[fm][0], a[fm][1], a[fm][2], a[fm][3],
                                b[bg][2], b[bg][3]);
                    } else {
                        MMA_F16(acc[fm][fn], a[fm][0], a[fm][1], a[fm][2], a[fm][3],
                                b[bg][0], b[bg][1]);
                    }
                }
        }
    }
    __syncthreads();

    const int g = lane >> 2;
    const int cpair = (lane & 3) * 2;
    if (round_out) {
        __half* Ch = (__half*)CoutV;
        #pragma unroll
        for (int fm = 0; fm < 2; fm++)
            #pragma unroll
            for (int fn = 0; fn < 8; fn++) {
                int r = m0 + wm * 32 + fm * 16 + g;
                int c = n0 + wn * 64 + fn * 8 + cpair;
                *(uint32_t*)&Ch[(size_t)r * N + c] =
                    packh2(acc[fm][fn][0], acc[fm][fn][1]);
                *(uint32_t*)&Ch[(size_t)(r + 8) * N + c] =
                    packh2(acc[fm][fn][2], acc[fm][fn][3]);
            }
    } else {
        float* Cf = (float*)CoutV;
        #pragma unroll
        for (int fm = 0; fm < 2; fm++)
            #pragma unroll
            for (int fn = 0; fn < 8; fn++) {
                int r = m0 + wm * 32 + fm * 16 + g;
                int c = n0 + wn * 64 + fn * 8 + cpair;
                *(float2*)&Cf[(size_t)r * N + c] =
                    make_float2(acc[fm][fn][0], acc[fm][fn][1]);
                *(float2*)&Cf[(size_t)(r + 8) * N + c] =
                    make_float2(acc[fm][fn][2], acc[fm][fn][3]);
            }
    }
}

// ===========================================================================
// Flash sliding-window attention — R8/R11 structure + mask elision + ex2.
// Masking active only on kt==0 (lower window edge) and kt==NKT-1 (causal);
// interior tiles are provably unmasked (q0, KT, MEMW all multiples of 64).
// ===========================================================================
#define QT 64
#define KT 64
#define NKT 5
#define PPU 36

#define AQ   0
#define AK   8192
#define AV   24576
#define AP   40960
#define APM  50176
#define APS  50688
#define ATTN_SMEM_BYTES 51200

__global__ __launch_bounds__(256, 2) void attn_flash(const __half* __restrict__ qkv,
                                                     __half* __restrict__ y,
                                                     int bfix) {
    extern __shared__ char shm[];
    float* pmax = (float*)(shm + APM);
    float* psum = (float*)(shm + APS);
    uint32_t* Pu = (uint32_t*)(shm + AP);

    const int tid  = threadIdx.x;
    const int lane = tid & 31;
    const int wid  = tid >> 5;
    const int wm   = wid & 3;
    const int wn   = wid >> 2;
    const int q0 = blockIdx.x * QT;
    const int h  = blockIdx.y;
    const int b  = bfix;
    const int kstart = q0 - MEMW;
    const int kt0 = (q0 < MEMW) ? (MEMW - q0) / KT : 0;

    const __half* qbase = qkv + (size_t)b * TT * QKVN + h * DD;
    const __half* kbase = qbase + CC;
    const __half* vbase = qbase + 2 * CC;

    const uint32_t uQ = smem_u32(shm) + AQ;
    const uint32_t uK = smem_u32(shm) + AK;
    const uint32_t uV = smem_u32(shm) + AV;

    const int a_row = (lane & 7) + ((lane >> 3) & 1) * 8;
    const int a_col = (lane >> 4) * 16;
    const int b_row = (lane & 7) + (lane >> 4) * 8;
    const int b_col = ((lane >> 3) & 1) * 16;
    const int g  = lane >> 2;
    const int c2 = (lane & 3) * 2;
    const int r0 = wm * 16 + g;

    #pragma unroll
    for (int it = 0; it < 2; it++) {
        int idx = it * 256 + tid;
        int row = idx >> 3;
        int cc  = idx & 7;
        cp_async16(uQ + SW128((uint32_t)(row * 128 + cc * 16)),
                   &qbase[(size_t)(q0 + row) * QKVN + cc * 8]);
    }
    auto issue_kv = [&](int kt) {
        const uint32_t boff = (kt & 1) * 8192;
        const int kb = kstart + kt * KT;
        #pragma unroll
        for (int it = 0; it < 2; it++) {
            int idx = it * 256 + tid;
            int row = idx >> 3;
            int cc  = idx & 7;
            int gk  = kb + row;
            uint32_t sw = SW128((uint32_t)(row * 128 + cc * 16));
            int ok = (gk >= 0) ? 16 : 0;
            const __half* ks = (gk >= 0) ? &kbase[(size_t)gk * QKVN + cc * 8] : kbase;
            const __half* vs = (gk >= 0) ? &vbase[(size_t)gk * QKVN + cc * 8] : vbase;
            cp_async16_z(uK + boff + sw, ks, ok);
            cp_async16_z(uV + boff + sw, vs, ok);
        }
    };
    issue_kv(kt0);
    CP_COMMIT();

    float m_old0 = -1e30f, m_old1 = -1e30f;
    float srun0 = 0.f, srun1 = 0.f;
    float oacc[4][4];
    #pragma unroll
    for (int i = 0; i < 4; i++)
        #pragma unroll
        for (int j = 0; j < 4; j++) oacc[i][j] = 0.f;

    for (int kt = kt0; kt < NKT; kt++) {
        CP_WAIT(0);
        __syncthreads();
        if (kt + 1 < NKT) { issue_kv(kt + 1); CP_COMMIT(); }

        const int kb = kstart + kt * KT;
        const uint32_t boff = (kt & 1) * 8192;

        float acc[4][4];
        #pragma unroll
        for (int i = 0; i < 4; i++)
            #pragma unroll
            for (int j = 0; j < 4; j++) acc[i][j] = 0.f;

        #pragma unroll
        for (int ks = 0; ks < 4; ks++) {
            uint32_t a[4];
            {
                int row = wm * 16 + a_row;
                LDSM_X4(a[0], a[1], a[2], a[3],
                        uQ + SW128((uint32_t)(row * 128 + ks * 32 + a_col)));
            }
            uint32_t bf[2][4];
            #pragma unroll
            for (int g2 = 0; g2 < 2; g2++) {
                int row = wn * 32 + g2 * 16 + b_row;
                LDSM_X4(bf[g2][0], bf[g2][1], bf[g2][2], bf[g2][3],
                        uK + boff + SW128((uint32_t)(row * 128 + ks * 32 + b_col)));
            }
            #pragma unroll
            for (int fn = 0; fn < 4; fn++) {
                const int bg = fn >> 1;
                if (fn & 1) {
                    MMA_F16(acc[fn], a[0], a[1], a[2], a[3], bf[bg][2], bf[bg][3]);
                } else {
                    MMA_F16(acc[fn], a[0], a[1], a[2], a[3], bf[bg][0], bf[bg][1]);
                }
            }
        }

        // ---- scale (+ mask only on edge tiles) + per-warp row max ----
        float mx0 = -1e30f, mx1 = -1e30f;
        if (kt == 0 || kt == NKT - 1) {
            const int qi0 = q0 + r0;
            const int qi1 = qi0 + 8;
            #pragma unroll
            for (int fn = 0; fn < 4; fn++) {
                int c  = wn * 32 + fn * 8 + c2;
                int kj = kb + c;
                #pragma unroll
                for (int jj = 0; jj < 2; jj++) {
                    int k = kj + jj;
                    bool ok0 = (k <= qi0) && (qi0 - k <= MEMW);
                    bool ok1 = (k <= qi1) && (qi1 - k <= MEMW);
                    acc[fn][jj]     = ok0 ? acc[fn][jj]     * SCL : -1e30f;
                    acc[fn][2 + jj] = ok1 ? acc[fn][2 + jj] * SCL : -1e30f;
                    mx0 = fmaxf(mx0, acc[fn][jj]);
                    mx1 = fmaxf(mx1, acc[fn][2 + jj]);
                }
            }
        } else {
            #pragma unroll
            for (int fn = 0; fn < 4; fn++) {
                #pragma unroll
                for (int jj = 0; jj < 2; jj++) {
                    acc[fn][jj]     *= SCL;
                    acc[fn][2 + jj] *= SCL;
                    mx0 = fmaxf(mx0, acc[fn][jj]);
                    mx1 = fmaxf(mx1, acc[fn][2 + jj]);
                }
            }
        }
        mx0 = fmaxf(mx0, __shfl_xor_sync(0xFFFFFFFF, mx0, 1));
        mx0 = fmaxf(mx0, __shfl_xor_sync(0xFFFFFFFF, mx0, 2));
        mx1 = fmaxf(mx1, __shfl_xor_sync(0xFFFFFFFF, mx1, 1));
        mx1 = fmaxf(mx1, __shfl_xor_sync(0xFFFFFFFF, mx1, 2));
        if ((lane & 3) == 0) {
            pmax[r0 * 2 + wn] = mx0;
            pmax[(r0 + 8) * 2 + wn] = mx1;
        }
        __syncthreads();

        float m0 = fmaxf(m_old0, fmaxf(pmax[r0 * 2], pmax[r0 * 2 + 1]));
        float m1 = fmaxf(m_old1, fmaxf(pmax[(r0 + 8) * 2], pmax[(r0 + 8) * 2 + 1]));
        float f0 = ex2f(m_old0 - m0);
        float f1 = ex2f(m_old1 - m1);
        m_old0 = m0;
        m_old1 = m1;

        float s0 = 0.f, s1 = 0.f;
        #pragma unroll
        for (int fn = 0; fn < 4; fn++) {
            int cu = wn * 16 + fn * 4 + (lane & 3);
            float p00 = ex2f(acc[fn][0] - m0);
            float p01 = ex2f(acc[fn][1] - m0);
            float p10 = ex2f(acc[fn][2] - m1);
            float p11 = ex2f(acc[fn][3] - m1);
            Pu[r0 * PPU + cu] = packh2(p00, p01);
            Pu[(r0 + 8) * PPU + cu] = packh2(p10, p11);
            s0 += p00 + p01;
            s1 += p10 + p11;
        }
        s0 += __shfl_xor_sync(0xFFFFFFFF, s0, 1);
        s0 += __shfl_xor_sync(0xFFFFFFFF, s0, 2);
        s1 += __shfl_xor_sync(0xFFFFFFFF, s1, 1);
        s1 += __shfl_xor_sync(0xFFFFFFFF, s1, 2);
        if ((lane & 3) == 0) {
            psum[r0 * 2 + wn] = s0;
            psum[(r0 + 8) * 2 + wn] = s1;
        }
        #pragma unroll
        for (int fn = 0; fn < 4; fn++) {
            oacc[fn][0] *= f0;
            oacc[fn][1] *= f0;
            oacc[fn][2] *= f1;
            oacc[fn][3] *= f1;
        }
        __syncthreads();

        srun0 = srun0 * f0 + psum[r0 * 2] + psum[r0 * 2 + 1];
        srun1 = srun1 * f1 + psum[(r0 + 8) * 2] + psum[(r0 + 8) * 2 + 1];

        #pragma unroll
        for (int ks = 0; ks < 4; ks++) {
            uint32_t a[4];
            {
                int base = ks * 8 + (lane & 3);
                a[0] = Pu[r0 * PPU + base];
                a[1] = Pu[(r0 + 8) * PPU + base];
                a[2] = Pu[r0 * PPU + base + 4];
                a[3] = Pu[(r0 + 8) * PPU + base + 4];
            }
            uint32_t bf[2][4];
            #pragma unroll
            for (int g2 = 0; g2 < 2; g2++) {
                int row = ks * 16 + (lane & 7) + ((lane >> 3) & 1) * 8;
                int bcol = wn * 64 + g2 * 32 + (lane >> 4) * 16;
                LDSM_X4T(bf[g2][0], bf[g2][1], bf[g2][2], bf[g2][3],
                         uV + boff + SW128((uint32_t)(row * 128 + bcol)));
            }
            #pragma unroll
            for (int fn = 0; fn < 4; fn++) {
                const int bg = fn >> 1;
                if (fn & 1) {
                    MMA_F16(oacc[fn], a[0], a[1], a[2], a[3], bf[bg][2], bf[bg][3]);
                } else {
                    MMA_F16(oacc[fn], a[0], a[1], a[2], a[3], bf[bg][0], bf[bg][1]);
                }
            }
        }
    }

    {
        float inv0 = 1.0f / srun0;
        float inv1 = 1.0f / srun1;
        #pragma unroll
        for (int fn = 0; fn < 4; fn++) {
            int col = wn * 32 + fn * 8 + c2;
            __half* p0 = &y[(size_t)(b * TT + q0 + r0) * CC + h * DD + col];
            __half* p1 = &y[(size_t)(b * TT + q0 + r0 + 8) * CC + h * DD + col];
            *(uint32_t*)p0 = packh2(oacc[fn][0] * inv0, oacc[fn][1] * inv0);
            *(uint32_t*)p1 = packh2(oacc[fn][2] * inv1, oacc[fn][3] * inv1);
        }
    }
}

// ===========================================================================
// launcher: 2-stream batch pipeline (unchanged from R11)
// ===========================================================================
extern "C" void kernel_launch(void* const* d_in, const int* in_sizes, int n_in,
                              void* d_out, int out_size) {
    const float* x      = (const float*)d_in[0];
    const float* w_attn = (const float*)d_in[1];
    const float* w_proj = (const float*)d_in[2];
    float* out = (float*)d_out;

    __half *qkv = nullptr, *yb = nullptr, *xc = nullptr, *wac = nullptr, *wpc = nullptr;
    cudaGetSymbolAddress((void**)&qkv, g_qkv);
    cudaGetSymbolAddress((void**)&yb,  g_y);
    cudaGetSymbolAddress((void**)&xc,  g_xc);
    cudaGetSymbolAddress((void**)&wac, g_wac);
    cudaGetSymbolAddress((void**)&wpc, g_wpc);

    cudaFuncSetAttribute(attn_flash,
                         cudaFuncAttributeMaxDynamicSharedMemorySize, ATTN_SMEM_BYTES);
    cudaFuncSetAttribute(gemm_fp16,
                         cudaFuncAttributeMaxDynamicSharedMemorySize, GEMM_SMEM);

    cudaStream_t s1;
    cudaStreamCreateWithFlags(&s1, cudaStreamNonBlocking);
    cudaEvent_t evQ0, evJoin;
    cudaEventCreateWithFlags(&evQ0,  cudaEventDisableTiming);
    cudaEventCreateWithFlags(&evJoin, cudaEventDisableTiming);

    const int MH = M_TOT / 2;

    {
        int total8 = (XN + WAN + WPN) / 8;
        convert_kernel<<<(total8 + 255) / 256, 256, 0, 0>>>(x, w_attn, w_proj);
    }
    {
        dim3 grid(QKVN / GBN, MH / GBM);
        gemm_fp16<<<grid, 256, GEMM_SMEM, 0>>>(xc, wac, qkv, M_TOT, QKVN, CC, 1, 0);
    }
    cudaEventRecord(evQ0, 0);
    cudaStreamWaitEvent(s1, evQ0, 0);

    {
        dim3 grid(QKVN / GBN, MH / GBM);
        gemm_fp16<<<grid, 256, GEMM_SMEM, s1>>>(xc, wac, qkv, M_TOT, QKVN, CC, 1, MH);
    }
    {
        dim3 grid(TT / QT, HH);
        attn_flash<<<grid, 256, ATTN_SMEM_BYTES, 0>>>(qkv, yb, 0);
    }
    {
        dim3 grid(CC / GBN, MH / GBM);
        gemm_fp16<<<grid, 256, GEMM_SMEM, 0>>>(yb, wpc, out, M_TOT, CC, CC, 0, 0);
    }
    {
        dim3 grid(TT / QT, HH);
        attn_flash<<<grid, 256, ATTN_SMEM_BYTES, s1>>>(qkv, yb, 1);
    }
    {
        dim3 grid(CC / GBN, MH / GBM);
        gemm_fp16<<<grid, 256, GEMM_SMEM, s1>>>(yb, wpc, out, M_TOT, CC, CC, 0, MH);
    }

    cudaEventRecord(evJoin, s1);
    cudaStreamWaitEvent(0, evJoin, 0);
}

// round 13
// speedup vs baseline: 1.0946x; 1.0271x over previous
#include <cuda_runtime.h>
#include <cuda_fp16.h>
#include <math.h>
#include <stdint.h>

#define BB   2
#define TT   4096
#define CC   512
#define HH   8
#define DD   64
#define MEMW 256

#define M_TOT (BB*TT)     // 8192
#define QKVN  (3*CC)      // 1536

#define XN  (M_TOT*CC)
#define WAN (QKVN*CC)
#define WPN (CC*CC)

// scratch (allocation-free contract: device globals) — fp16
__device__ __half g_qkv[BB*TT*3*CC];
__device__ __half g_y[BB*TT*CC];
__device__ __half g_xc[XN];
__device__ __half g_wac[WAN];
__device__ __half g_wpc[WPN];

// ===========================================================================
// helpers
// ===========================================================================
__device__ __forceinline__ uint32_t smem_u32(const void* p) {
    uint32_t a;
    asm("{ .reg .u64 t; cvta.to.shared.u64 t, %1; cvt.u32.u64 %0, t; }"
        : "=r"(a) : "l"(p));
    return a;
}
#define SW128(off) ((off) ^ (((off) >> 3) & 0x70))

#define LDSM_X4(r0, r1, r2, r3, addr) \
    asm volatile("ldmatrix.sync.aligned.m8n8.x4.shared.b16 {%0,%1,%2,%3}, [%4];" \
                 : "=r"(r0), "=r"(r1), "=r"(r2), "=r"(r3) : "r"(addr))

#define LDSM_X4T(r0, r1, r2, r3, addr) \
    asm volatile("ldmatrix.sync.aligned.m8n8.x4.trans.shared.b16 {%0,%1,%2,%3}, [%4];" \
                 : "=r"(r0), "=r"(r1), "=r"(r2), "=r"(r3) : "r"(addr))

#define MMA_F16(c, a0, a1, a2, a3, b0, b1) \
    asm volatile("mma.sync.aligned.m16n8k16.row.col.f32.f16.f16.f32 " \
                 "{%0,%1,%2,%3}, {%4,%5,%6,%7}, {%8,%9}, {%0,%1,%2,%3};" \
                 : "+f"((c)[0]), "+f"((c)[1]), "+f"((c)[2]), "+f"((c)[3]) \
                 : "r"(a0), "r"(a1), "r"(a2), "r"(a3), "r"(b0), "r"(b1))

__device__ __forceinline__ void cp_async16(uint32_t s, const void* g) {
    asm volatile("cp.async.cg.shared.global [%0], [%1], 16;"
                 :: "r"(s), "l"(__cvta_generic_to_global(g)));
}
__device__ __forceinline__ void cp_async16_z(uint32_t s, const void* g, int sz) {
    asm volatile("cp.async.cg.shared.global [%0], [%1], 16, %2;"
                 :: "r"(s), "l"(__cvta_generic_to_global(g)), "r"(sz));
}
#define CP_COMMIT() asm volatile("cp.async.commit_group;" ::: "memory")
#define CP_WAIT(n)  asm volatile("cp.async.wait_group %0;" :: "n"(n) : "memory")
#define BAR_PAIR(id) asm volatile("bar.sync %0, 64;" :: "r"(id) : "memory")

__device__ __forceinline__ uint32_t packh2(float a, float b) {
    __half2 h = __floats2half2_rn(a, b);
    return *(uint32_t*)&h;
}
__device__ __forceinline__ float ex2f(float x) {
    float r;
    asm("ex2.approx.f32 %0, %1;" : "=f"(r) : "f"(x));
    return r;
}

// scores pre-scaled by 1/sqrt(d) * log2(e) so softmax uses raw ex2
#define SCL 0.18033688011112042f

// ===========================================================================
// pre-convert: fp32 -> fp16 for x, w_attn, w_proj  (unchanged)
// ===========================================================================
__global__ __launch_bounds__(256) void convert_kernel(const float* __restrict__ x,
                                                      const float* __restrict__ wa,
                                                      const float* __restrict__ wp) {
    const int i8 = blockIdx.x * 256 + threadIdx.x;
    const int total8 = (XN + WAN + WPN) / 8;
    if (i8 >= total8) return;
    const float* src;
    __half* dst;
    int j = i8;
    if (j < XN / 8)                   { src = x;  dst = g_xc; }
    else if ((j -= XN / 8) < WAN / 8) { src = wa; dst = g_wac; }
    else                              { j -= WAN / 8; src = wp; dst = g_wpc; }
    float4 v0 = ((const float4*)src)[j * 2];
    float4 v1 = ((const float4*)src)[j * 2 + 1];
    uint4 o = make_uint4(packh2(v0.x, v0.y), packh2(v0.z, v0.w),
                         packh2(v1.x, v1.y), packh2(v1.z, v1.w));
    ((uint4*)dst)[j] = o;
}

// ===========================================================================
// fp16 mma.sync GEMM (NT) — unchanged from R12
// ===========================================================================
#define GBM 128
#define GBN 128
#define GBK 64
#define STAGES 3
#define TILE_B (GBM * 128)
#define STAGE_B (2 * TILE_B)
#define GEMM_SMEM (STAGES * STAGE_B)    // 98304

__global__ __launch_bounds__(256) void gemm_fp16(const __half* __restrict__ A,
                                                 const __half* __restrict__ W,
                                                 void* __restrict__ CoutV,
                                                 int M, int N, int K,
                                                 int round_out, int mbase) {
    extern __shared__ char dynsm[];
    const uint32_t smb = smem_u32(dynsm);

    const int tid  = threadIdx.x;
    const int lane = tid & 31;
    const int wid  = tid >> 5;
    const int wm   = wid & 3;
    const int wn   = wid >> 2;
    const int m0 = mbase + blockIdx.y * GBM;
    const int n0 = blockIdx.x * GBN;

    const int crow = tid >> 3;
    const int cc   = tid & 7;
    const uint32_t cbyte = SW128((uint32_t)(crow * 128 + cc * 16));

    const int nk = K / GBK;

    auto issue_copy = [&](int kt) {
        const int s = kt % STAGES;
        const int k0 = kt * GBK;
        const uint32_t sa = smb + s * STAGE_B;
        const uint32_t sb = sa + TILE_B;
        #pragma unroll
        for (int it = 0; it < 4; it++) {
            const int row = crow + it * 32;
            cp_async16(sa + cbyte + it * 32 * 128,
                       &A[(size_t)(m0 + row) * K + k0 + cc * 8]);
        }
        #pragma unroll
        for (int it = 0; it < 4; it++) {
            const int row = crow + it * 32;
            cp_async16(sb + cbyte + it * 32 * 128,
                       &W[(size_t)(n0 + row) * K + k0 + cc * 8]);
        }
    };

    float acc[2][8][4];
    #pragma unroll
    for (int i = 0; i < 2; i++)
        #pragma unroll
        for (int j = 0; j < 8; j++)
            #pragma unroll
            for (int k = 0; k < 4; k++) acc[i][j][k] = 0.f;

    const int a_row = (lane & 7) + ((lane >> 3) & 1) * 8;
    const int a_col = (lane >> 4) * 16;
    const int b_row = (lane & 7) + (lane >> 4) * 8;
    const int b_col = ((lane >> 3) & 1) * 16;

    #pragma unroll
    for (int s = 0; s < STAGES - 1; s++) {
        issue_copy(s);
        CP_COMMIT();
    }

    for (int kt = 0; kt < nk; kt++) {
        CP_WAIT(STAGES - 2);
        __syncthreads();
        if (kt + STAGES - 1 < nk) issue_copy(kt + STAGES - 1);
        CP_COMMIT();

        const uint32_t sa = smb + (kt % STAGES) * STAGE_B;
        const uint32_t sb = sa + TILE_B;

        #pragma unroll
        for (int ks = 0; ks < 4; ks++) {
            uint32_t a[2][4];
            #pragma unroll
            for (int fm = 0; fm < 2; fm++) {
                int row = wm * 32 + fm * 16 + a_row;
                LDSM_X4(a[fm][0], a[fm][1], a[fm][2], a[fm][3],
                        sa + SW128((uint32_t)(row * 128 + ks * 32 + a_col)));
            }
            uint32_t b[4][4];
            #pragma unroll
            for (int bg = 0; bg < 4; bg++) {
                int row = wn * 64 + bg * 16 + b_row;
                LDSM_X4(b[bg][0], b[bg][1], b[bg][2], b[bg][3],
                        sb + SW128((uint32_t)(row * 128 + ks * 32 + b_col)));
            }
            #pragma unroll
            for (int fm = 0; fm < 2; fm++)
                #pragma unroll
                for (int fn = 0; fn < 8; fn++) {
                    const int bg = fn >> 1;
                    if (fn & 1) {
                        MMA_F16(acc[fm][fn], a[fm][0], a[fm][1], a[fm][2], a[fm][3],
                                b[bg][2], b[bg][3]);
                    } else {
                        MMA_F16(acc[fm][fn], a[fm][0], a[fm][1], a[fm][2], a[fm][3],
                                b[bg][0], b[bg][1]);
                    }
                }
        }
    }
    __syncthreads();

    const int g = lane >> 2;
    const int cpair = (lane & 3) * 2;
    if (round_out) {
        __half* Ch = (__half*)CoutV;
        #pragma unroll
        for (int fm = 0; fm < 2; fm++)
            #pragma unroll
            for (int fn = 0; fn < 8; fn++) {
                int r = m0 + wm * 32 + fm * 16 + g;
                int c = n0 + wn * 64 + fn * 8 + cpair;
                *(uint32_t*)&Ch[(size_t)r * N + c] =
                    packh2(acc[fm][fn][0], acc[fm][fn][1]);
                *(uint32_t*)&Ch[(size_t)(r + 8) * N + c] =
                    packh2(acc[fm][fn][2], acc[fm][fn][3]);
            }
    } else {
        float* Cf = (float*)CoutV;
        #pragma unroll
        for (int fm = 0; fm < 2; fm++)
            #pragma unroll
            for (int fn = 0; fn < 8; fn++) {
                int r = m0 + wm * 32 + fm * 16 + g;
                int c = n0 + wn * 64 + fn * 8 + cpair;
                *(float2*)&Cf[(size_t)r * N + c] =
                    make_float2(acc[fm][fn][0], acc[fm][fn][1]);
                *(float2*)&Cf[(size_t)(r + 8) * N + c] =
                    make_float2(acc[fm][fn][2], acc[fm][fn][3]);
            }
    }
}

// ===========================================================================
// Flash sliding-window attention v4: P kept in REGISTERS (score-C == PV-A
// fragment identity). Warp wn multiplies only its 32 keys against all 64 d;
// O/l partials reduced across the warp pair once in the epilogue.
// Per tile: 1 CTA sync (KV buffers) + 1 two-warp named barrier (row max).
// ===========================================================================
#define QT 64
#define KT 64
#define NKT 5
#define OBP 72            // O exchange row pitch (floats)

#define AQ   0            // 8192
#define AK   8192         // 2 x 8192
#define AV   24576        // 2 x 8192
#define APM  40960        // pmax 64 rows x 2 x 4B = 512
#define AOB  41472        // O exchange: 64 rows x OBP x 4B = 18432
#define ASR  59904        // srun exchange: 64 x 4B = 256
#define ATTN_SMEM_BYTES 60160

__global__ __launch_bounds__(256, 2) void attn_flash(const __half* __restrict__ qkv,
                                                     __half* __restrict__ y,
                                                     int bfix) {
    extern __shared__ char shm[];
    float* pmax = (float*)(shm + APM);
    float* Obuf = (float*)(shm + AOB);
    float* Sr   = (float*)(shm + ASR);

    const int tid  = threadIdx.x;
    const int lane = tid & 31;
    const int wid  = tid >> 5;
    const int wm   = wid & 3;           // row block (16 rows)
    const int wn   = wid >> 2;          // key half (32 keys)
    const int q0 = blockIdx.x * QT;
    const int h  = blockIdx.y;
    const int b  = bfix;
    const int kstart = q0 - MEMW;
    const int kt0 = (q0 < MEMW) ? (MEMW - q0) / KT : 0;

    const __half* qbase = qkv + (size_t)b * TT * QKVN + h * DD;
    const __half* kbase = qbase + CC;
    const __half* vbase = qbase + 2 * CC;

    const uint32_t uQ = smem_u32(shm) + AQ;
    const uint32_t uK = smem_u32(shm) + AK;
    const uint32_t uV = smem_u32(shm) + AV;

    const int a_row = (lane & 7) + ((lane >> 3) & 1) * 8;
    const int a_col = (lane >> 4) * 16;
    const int b_row = (lane & 7) + (lane >> 4) * 8;
    const int b_col = ((lane >> 3) & 1) * 16;
    const int g  = lane >> 2;
    const int c2 = (lane & 3) * 2;
    const int r0 = wm * 16 + g;

    #pragma unroll
    for (int it = 0; it < 2; it++) {
        int idx = it * 256 + tid;
        int row = idx >> 3;
        int cc  = idx & 7;
        cp_async16(uQ + SW128((uint32_t)(row * 128 + cc * 16)),
                   &qbase[(size_t)(q0 + row) * QKVN + cc * 8]);
    }
    auto issue_kv = [&](int kt) {
        const uint32_t boff = (kt & 1) * 8192;
        const int kb = kstart + kt * KT;
        #pragma unroll
        for (int it = 0; it < 2; it++) {
            int idx = it * 256 + tid;
            int row = idx >> 3;
            int cc  = idx & 7;
            int gk  = kb + row;
            uint32_t sw = SW128((uint32_t)(row * 128 + cc * 16));
            int ok = (gk >= 0) ? 16 : 0;
            const __half* ks = (gk >= 0) ? &kbase[(size_t)gk * QKVN + cc * 8] : kbase;
            const __half* vs = (gk >= 0) ? &vbase[(size_t)gk * QKVN + cc * 8] : vbase;
            cp_async16_z(uK + boff + sw, ks, ok);
            cp_async16_z(uV + boff + sw, vs, ok);
        }
    };
    issue_kv(kt0);
    CP_COMMIT();

    float m_old0 = -1e30f, m_old1 = -1e30f;
    float srun0 = 0.f, srun1 = 0.f;
    float oacc[8][4];                   // 16 rows x 64 d (warp-partial over keys)
    #pragma unroll
    for (int i = 0; i < 8; i++)
        #pragma unroll
        for (int j = 0; j < 4; j++) oacc[i][j] = 0.f;

    for (int kt = kt0; kt < NKT; kt++) {
        CP_WAIT(0);
        __syncthreads();               // KV(kt) visible; all warps past tile kt-1
        if (kt + 1 < NKT) { issue_kv(kt + 1); CP_COMMIT(); }

        const int kb = kstart + kt * KT;
        const uint32_t boff = (kt & 1) * 8192;

        // ---- scores: Q(16 rows) x K^T(this warp's 32 keys) ----
        float acc[4][4];
        #pragma unroll
        for (int i = 0; i < 4; i++)
            #pragma unroll
            for (int j = 0; j < 4; j++) acc[i][j] = 0.f;

        #pragma unroll
        for (int ks = 0; ks < 4; ks++) {
            uint32_t a[4];
            {
                int row = wm * 16 + a_row;
                LDSM_X4(a[0], a[1], a[2], a[3],
                        uQ + SW128((uint32_t)(row * 128 + ks * 32 + a_col)));
            }
            uint32_t bf[2][4];
            #pragma unroll
            for (int g2 = 0; g2 < 2; g2++) {
                int row = wn * 32 + g2 * 16 + b_row;
                LDSM_X4(bf[g2][0], bf[g2][1], bf[g2][2], bf[g2][3],
                        uK + boff + SW128((uint32_t)(row * 128 + ks * 32 + b_col)));
            }
            #pragma unroll
            for (int fn = 0; fn < 4; fn++) {
                const int bg = fn >> 1;
                if (fn & 1) {
                    MMA_F16(acc[fn], a[0], a[1], a[2], a[3], bf[bg][2], bf[bg][3]);
                } else {
                    MMA_F16(acc[fn], a[0], a[1], a[2], a[3], bf[bg][0], bf[bg][1]);
                }
            }
        }

        // ---- scale (+ mask only on edge tiles) + quad row max ----
        float mx0 = -1e30f, mx1 = -1e30f;
        if (kt == 0 || kt == NKT - 1) {
            const int qi0 = q0 + r0;
            const int qi1 = qi0 + 8;
            #pragma unroll
            for (int fn = 0; fn < 4; fn++) {
                int c  = wn * 32 + fn * 8 + c2;
                int kj = kb + c;
                #pragma unroll
                for (int jj = 0; jj < 2; jj++) {
                    int k = kj + jj;
                    bool ok0 = (k <= qi0) && (qi0 - k <= MEMW);
                    bool ok1 = (k <= qi1) && (qi1 - k <= MEMW);
                    acc[fn][jj]     = ok0 ? acc[fn][jj]     * SCL : -1e30f;
                    acc[fn][2 + jj] = ok1 ? acc[fn][2 + jj] * SCL : -1e30f;
                    mx0 = fmaxf(mx0, acc[fn][jj]);
                    mx1 = fmaxf(mx1, acc[fn][2 + jj]);
                }
            }
        } else {
            #pragma unroll
            for (int fn = 0; fn < 4; fn++) {
                #pragma unroll
                for (int jj = 0; jj < 2; jj++) {
                    acc[fn][jj]     *= SCL;
                    acc[fn][2 + jj] *= SCL;
                    mx0 = fmaxf(mx0, acc[fn][jj]);
                    mx1 = fmaxf(mx1, acc[fn][2 + jj]);
                }
            }
        }
        mx0 = fmaxf(mx0, __shfl_xor_sync(0xFFFFFFFF, mx0, 1));
        mx0 = fmaxf(mx0, __shfl_xor_sync(0xFFFFFFFF, mx0, 2));
        mx1 = fmaxf(mx1, __shfl_xor_sync(0xFFFFFFFF, mx1, 1));
        mx1 = fmaxf(mx1, __shfl_xor_sync(0xFFFFFFFF, mx1, 2));

        // ---- cross-warp (pair) max exchange via named barrier ----
        if ((lane & 3) == 0) {
            pmax[r0 * 2 + wn] = mx0;
            pmax[(r0 + 8) * 2 + wn] = mx1;
        }
        BAR_PAIR(wm + 1);
        float m0 = fmaxf(m_old0, fmaxf(pmax[r0 * 2], pmax[r0 * 2 + 1]));
        float m1 = fmaxf(m_old1, fmaxf(pmax[(r0 + 8) * 2], pmax[(r0 + 8) * 2 + 1]));
        float f0 = ex2f(m_old0 - m0);
        float f1 = ex2f(m_old1 - m1);
        m_old0 = m0;
        m_old1 = m1;

        // ---- exp into PV A-fragments (registers; no smem) + partial sums ----
        uint32_t aP[2][4];
        float s0 = 0.f, s1 = 0.f;
        #pragma unroll
        for (int kk = 0; kk < 2; kk++) {
            float p00 = ex2f(acc[2*kk][0] - m0);
            float p01 = ex2f(acc[2*kk][1] - m0);
            float p02 = ex2f(acc[2*kk][2] - m1);
            float p03 = ex2f(acc[2*kk][3] - m1);
            float p10 = ex2f(acc[2*kk+1][0] - m0);
            float p11 = ex2f(acc[2*kk+1][1] - m0);
            float p12 = ex2f(acc[2*kk+1][2] - m1);
            float p13 = ex2f(acc[2*kk+1][3] - m1);
            aP[kk][0] = packh2(p00, p01);
            aP[kk][1] = packh2(p02, p03);
            aP[kk][2] = packh2(p10, p11);
            aP[kk][3] = packh2(p12, p13);
            s0 += p00 + p01 + p10 + p11;
            s1 += p02 + p03 + p12 + p13;
        }
        s0 += __shfl_xor_sync(0xFFFFFFFF, s0, 1);
        s0 += __shfl_xor_sync(0xFFFFFFFF, s0, 2);
        s1 += __shfl_xor_sync(0xFFFFFFFF, s1, 1);
        s1 += __shfl_xor_sync(0xFFFFFFFF, s1, 2);
        srun0 = srun0 * f0 + s0;
        srun1 = srun1 * f1 + s1;

        #pragma unroll
        for (int fn = 0; fn < 8; fn++) {
            oacc[fn][0] *= f0;
            oacc[fn][1] *= f0;
            oacc[fn][2] *= f1;
            oacc[fn][3] *= f1;
        }

        // ---- PV: O(16 x 64d) += P(16 x this warp's 32 keys) x V ----
        #pragma unroll
        for (int kk = 0; kk < 2; kk++) {
            uint32_t bf[4][4];
            #pragma unroll
            for (int g2 = 0; g2 < 4; g2++) {
                int row = wn * 32 + kk * 16 + (lane & 7) + ((lane >> 3) & 1) * 8;
                int bcol = g2 * 32 + (lane >> 4) * 16;
                LDSM_X4T(bf[g2][0], bf[g2][1], bf[g2][2], bf[g2][3],
                         uV + boff + SW128((uint32_t)(row * 128 + bcol)));
            }
            #pragma unroll
            for (int fn = 0; fn < 8; fn++) {
                const int bg = fn >> 1;
                if (fn & 1) {
                    MMA_F16(oacc[fn], aP[kk][0], aP[kk][1], aP[kk][2], aP[kk][3],
                            bf[bg][2], bf[bg][3]);
                } else {
                    MMA_F16(oacc[fn], aP[kk][0], aP[kk][1], aP[kk][2], aP[kk][3],
                            bf[bg][0], bf[bg][1]);
                }
            }
        }
    }

    // ---- epilogue: reduce O/l across the warp pair, normalize, store ----
    if (wn == 1) {
        #pragma unroll
        for (int fn = 0; fn < 8; fn++) {
            int col = fn * 8 + c2;
            float* d0 = &Obuf[(size_t)r0 * OBP + col];
            float* d1 = &Obuf[(size_t)(r0 + 8) * OBP + col];
            d0[0] = oacc[fn][0]; d0[1] = oacc[fn][1];
            d1[0] = oacc[fn][2]; d1[1] = oacc[fn][3];
        }
        if ((lane & 3) == 0) {
            Sr[r0] = srun0;
            Sr[r0 + 8] = srun1;
        }
    }
    BAR_PAIR(wm + 1);
    if (wn == 0) {
        float inv0 = 1.0f / (srun0 + Sr[r0]);
        float inv1 = 1.0f / (srun1 + Sr[r0 + 8]);
        #pragma unroll
        for (int fn = 0; fn < 8; fn++) {
            int col = fn * 8 + c2;
            const float* s0p = &Obuf[(size_t)r0 * OBP + col];
            const float* s1p = &Obuf[(size_t)(r0 + 8) * OBP + col];
            __half* p0 = &y[(size_t)(b * TT + q0 + r0) * CC + h * DD + col];
            __half* p1 = &y[(size_t)(b * TT + q0 + r0 + 8) * CC + h * DD + col];
            *(uint32_t*)p0 = packh2((oacc[fn][0] + s0p[0]) * inv0,
                                    (oacc[fn][1] + s0p[1]) * inv0);
            *(uint32_t*)p1 = packh2((oacc[fn][2] + s1p[0]) * inv1,
                                    (oacc[fn][3] + s1p[1]) * inv1);
        }
    }
}

// ===========================================================================
// launcher: 2-stream batch pipeline (unchanged from R12)
// ===========================================================================
extern "C" void kernel_launch(void* const* d_in, const int* in_sizes, int n_in,
                              void* d_out, int out_size) {
    const float* x      = (const float*)d_in[0];
    const float* w_attn = (const float*)d_in[1];
    const float* w_proj = (const float*)d_in[2];
    float* out = (float*)d_out;

    __half *qkv = nullptr, *yb = nullptr, *xc = nullptr, *wac = nullptr, *wpc = nullptr;
    cudaGetSymbolAddress((void**)&qkv, g_qkv);
    cudaGetSymbolAddress((void**)&yb,  g_y);
    cudaGetSymbolAddress((void**)&xc,  g_xc);
    cudaGetSymbolAddress((void**)&wac, g_wac);
    cudaGetSymbolAddress((void**)&wpc, g_wpc);

    cudaFuncSetAttribute(attn_flash,
                         cudaFuncAttributeMaxDynamicSharedMemorySize, ATTN_SMEM_BYTES);
    cudaFuncSetAttribute(gemm_fp16,
                         cudaFuncAttributeMaxDynamicSharedMemorySize, GEMM_SMEM);

    cudaStream_t s1;
    cudaStreamCreateWithFlags(&s1, cudaStreamNonBlocking);
    cudaEvent_t evQ0, evJoin;
    cudaEventCreateWithFlags(&evQ0,  cudaEventDisableTiming);
    cudaEventCreateWithFlags(&evJoin, cudaEventDisableTiming);

    const int MH = M_TOT / 2;

    {
        int total8 = (XN + WAN + WPN) / 8;
        convert_kernel<<<(total8 + 255) / 256, 256, 0, 0>>>(x, w_attn, w_proj);
    }
    {
        dim3 grid(QKVN / GBN, MH / GBM);
        gemm_fp16<<<grid, 256, GEMM_SMEM, 0>>>(xc, wac, qkv, M_TOT, QKVN, CC, 1, 0);
    }
    cudaEventRecord(evQ0, 0);
    cudaStreamWaitEvent(s1, evQ0, 0);

    {
        dim3 grid(QKVN / GBN, MH / GBM);
        gemm_fp16<<<grid, 256, GEMM_SMEM, s1>>>(xc, wac, qkv, M_TOT, QKVN, CC, 1, MH);
    }
    {
        dim3 grid(TT / QT, HH);
        attn_flash<<<grid, 256, ATTN_SMEM_BYTES, 0>>>(qkv, yb, 0);
    }
    {
        dim3 grid(CC / GBN, MH / GBM);
        gemm_fp16<<<grid, 256, GEMM_SMEM, 0>>>(yb, wpc, out, M_TOT, CC, CC, 0, 0);
    }
    {
        dim3 grid(TT / QT, HH);
        attn_flash<<<grid, 256, ATTN_SMEM_BYTES, s1>>>(qkv, yb, 1);
    }
    {
        dim3 grid(CC / GBN, MH / GBM);
        gemm_fp16<<<grid, 256, GEMM_SMEM, s1>>>(yb, wpc, out, M_TOT, CC, CC, 0, MH);
    }

    cudaEventRecord(evJoin, s1);
    cudaStreamWaitEvent(0, evJoin, 0);
}

// round 14
// speedup vs baseline: 1.1113x; 1.0153x over previous
#include <cuda_runtime.h>
#include <cuda_fp16.h>
#include <math.h>
#include <stdint.h>

#define BB   2
#define TT   4096
#define CC   512
#define HH   8
#define DD   64
#define MEMW 256

#define M_TOT (BB*TT)     // 8192
#define QKVN  (3*CC)      // 1536

#define XN  (M_TOT*CC)
#define WAN (QKVN*CC)
#define WPN (CC*CC)

// scratch (allocation-free contract: device globals) — fp16
__device__ __half g_qkv[BB*TT*3*CC];
__device__ __half g_y[BB*TT*CC];
__device__ __half g_xc[XN];
__device__ __half g_wac[WAN];
__device__ __half g_wpc[WPN];

// ===========================================================================
// helpers
// ===========================================================================
__device__ __forceinline__ uint32_t smem_u32(const void* p) {
    uint32_t a;
    asm("{ .reg .u64 t; cvta.to.shared.u64 t, %1; cvt.u32.u64 %0, t; }"
        : "=r"(a) : "l"(p));
    return a;
}
#define SW128(off) ((off) ^ (((off) >> 3) & 0x70))

#define LDSM_X4(r0, r1, r2, r3, addr) \
    asm volatile("ldmatrix.sync.aligned.m8n8.x4.shared.b16 {%0,%1,%2,%3}, [%4];" \
                 : "=r"(r0), "=r"(r1), "=r"(r2), "=r"(r3) : "r"(addr))

#define LDSM_X4T(r0, r1, r2, r3, addr) \
    asm volatile("ldmatrix.sync.aligned.m8n8.x4.trans.shared.b16 {%0,%1,%2,%3}, [%4];" \
                 : "=r"(r0), "=r"(r1), "=r"(r2), "=r"(r3) : "r"(addr))

#define MMA_F16(c, a0, a1, a2, a3, b0, b1) \
    asm volatile("mma.sync.aligned.m16n8k16.row.col.f32.f16.f16.f32 " \
                 "{%0,%1,%2,%3}, {%4,%5,%6,%7}, {%8,%9}, {%0,%1,%2,%3};" \
                 : "+f"((c)[0]), "+f"((c)[1]), "+f"((c)[2]), "+f"((c)[3]) \
                 : "r"(a0), "r"(a1), "r"(a2), "r"(a3), "r"(b0), "r"(b1))

__device__ __forceinline__ void cp_async16(uint32_t s, const void* g) {
    asm volatile("cp.async.cg.shared.global [%0], [%1], 16;"
                 :: "r"(s), "l"(__cvta_generic_to_global(g)));
}
__device__ __forceinline__ void cp_async16_z(uint32_t s, const void* g, int sz) {
    asm volatile("cp.async.cg.shared.global [%0], [%1], 16, %2;"
                 :: "r"(s), "l"(__cvta_generic_to_global(g)), "r"(sz));
}
#define CP_COMMIT() asm volatile("cp.async.commit_group;" ::: "memory")
#define CP_WAIT(n)  asm volatile("cp.async.wait_group %0;" :: "n"(n) : "memory")
#define BAR_PAIR(id) asm volatile("bar.sync %0, 64;" :: "r"(id) : "memory")

__device__ __forceinline__ uint32_t packh2(float a, float b) {
    __half2 h = __floats2half2_rn(a, b);
    return *(uint32_t*)&h;
}
__device__ __forceinline__ float ex2f(float x) {
    float r;
    asm("ex2.approx.f32 %0, %1;" : "=f"(r) : "f"(x));
    return r;
}

// scores pre-scaled by 1/sqrt(d) * log2(e) so softmax uses raw ex2
#define SCL 0.18033688011112042f

// ===========================================================================
// pre-convert: fp32 -> fp16 for x, w_attn, w_proj  (unchanged)
// ===========================================================================
__global__ __launch_bounds__(256) void convert_kernel(const float* __restrict__ x,
                                                      const float* __restrict__ wa,
                                                      const float* __restrict__ wp) {
    const int i8 = blockIdx.x * 256 + threadIdx.x;
    const int total8 = (XN + WAN + WPN) / 8;
    if (i8 >= total8) return;
    const float* src;
    __half* dst;
    int j = i8;
    if (j < XN / 8)                   { src = x;  dst = g_xc; }
    else if ((j -= XN / 8) < WAN / 8) { src = wa; dst = g_wac; }
    else                              { j -= WAN / 8; src = wp; dst = g_wpc; }
    float4 v0 = ((const float4*)src)[j * 2];
    float4 v1 = ((const float4*)src)[j * 2 + 1];
    uint4 o = make_uint4(packh2(v0.x, v0.y), packh2(v0.z, v0.w),
                         packh2(v1.x, v1.y), packh2(v1.z, v1.w));
    ((uint4*)dst)[j] = o;
}

// ===========================================================================
// fp16 mma.sync GEMM (NT) — unchanged from R13
// ===========================================================================
#define GBM 128
#define GBN 128
#define GBK 64
#define STAGES 3
#define TILE_B (GBM * 128)
#define STAGE_B (2 * TILE_B)
#define GEMM_SMEM (STAGES * STAGE_B)    // 98304

__global__ __launch_bounds__(256) void gemm_fp16(const __half* __restrict__ A,
                                                 const __half* __restrict__ W,
                                                 void* __restrict__ CoutV,
                                                 int M, int N, int K,
                                                 int round_out, int mbase) {
    extern __shared__ char dynsm[];
    const uint32_t smb = smem_u32(dynsm);

    const int tid  = threadIdx.x;
    const int lane = tid & 31;
    const int wid  = tid >> 5;
    const int wm   = wid & 3;
    const int wn   = wid >> 2;
    const int m0 = mbase + blockIdx.y * GBM;
    const int n0 = blockIdx.x * GBN;

    const int crow = tid >> 3;
    const int cc   = tid & 7;
    const uint32_t cbyte = SW128((uint32_t)(crow * 128 + cc * 16));

    const int nk = K / GBK;

    auto issue_copy = [&](int kt) {
        const int s = kt % STAGES;
        const int k0 = kt * GBK;
        const uint32_t sa = smb + s * STAGE_B;
        const uint32_t sb = sa + TILE_B;
        #pragma unroll
        for (int it = 0; it < 4; it++) {
            const int row = crow + it * 32;
            cp_async16(sa + cbyte + it * 32 * 128,
                       &A[(size_t)(m0 + row) * K + k0 + cc * 8]);
        }
        #pragma unroll
        for (int it = 0; it < 4; it++) {
            const int row = crow + it * 32;
            cp_async16(sb + cbyte + it * 32 * 128,
                       &W[(size_t)(n0 + row) * K + k0 + cc * 8]);
        }
    };

    float acc[2][8][4];
    #pragma unroll
    for (int i = 0; i < 2; i++)
        #pragma unroll
        for (int j = 0; j < 8; j++)
            #pragma unroll
            for (int k = 0; k < 4; k++) acc[i][j][k] = 0.f;

    const int a_row = (lane & 7) + ((lane >> 3) & 1) * 8;
    const int a_col = (lane >> 4) * 16;
    const int b_row = (lane & 7) + (lane >> 4) * 8;
    const int b_col = ((lane >> 3) & 1) * 16;

    #pragma unroll
    for (int s = 0; s < STAGES - 1; s++) {
        issue_copy(s);
        CP_COMMIT();
    }

    for (int kt = 0; kt < nk; kt++) {
        CP_WAIT(STAGES - 2);
        __syncthreads();
        if (kt + STAGES - 1 < nk) issue_copy(kt + STAGES - 1);
        CP_COMMIT();

        const uint32_t sa = smb + (kt % STAGES) * STAGE_B;
        const uint32_t sb = sa + TILE_B;

        #pragma unroll
        for (int ks = 0; ks < 4; ks++) {
            uint32_t a[2][4];
            #pragma unroll
            for (int fm = 0; fm < 2; fm++) {
                int row = wm * 32 + fm * 16 + a_row;
                LDSM_X4(a[fm][0], a[fm][1], a[fm][2], a[fm][3],
                        sa + SW128((uint32_t)(row * 128 + ks * 32 + a_col)));
            }
            uint32_t b[4][4];
            #pragma unroll
            for (int bg = 0; bg < 4; bg++) {
                int row = wn * 64 + bg * 16 + b_row;
                LDSM_X4(b[bg][0], b[bg][1], b[bg][2], b[bg][3],
                        sb + SW128((uint32_t)(row * 128 + ks * 32 + b_col)));
            }
            #pragma unroll
            for (int fm = 0; fm < 2; fm++)
                #pragma unroll
                for (int fn = 0; fn < 8; fn++) {
                    const int bg = fn >> 1;
                    if (fn & 1) {
                        MMA_F16(acc[fm][fn], a[fm][0], a[fm][1], a[fm][2], a[fm][3],
                                b[bg][2], b[bg][3]);
                    } else {
                        MMA_F16(acc[fm][fn], a[fm][0], a[fm][1], a[fm][2], a[fm][3],
                                b[bg][0], b[bg][1]);
                    }
                }
        }
    }
    __syncthreads();

    const int g = lane >> 2;
    const int cpair = (lane & 3) * 2;
    if (round_out) {
        __half* Ch = (__half*)CoutV;
        #pragma unroll
        for (int fm = 0; fm < 2; fm++)
            #pragma unroll
            for (int fn = 0; fn < 8; fn++) {
                int r = m0 + wm * 32 + fm * 16 + g;
                int c = n0 + wn * 64 + fn * 8 + cpair;
                *(uint32_t*)&Ch[(size_t)r * N + c] =
                    packh2(acc[fm][fn][0], acc[fm][fn][1]);
                *(uint32_t*)&Ch[(size_t)(r + 8) * N + c] =
                    packh2(acc[fm][fn][2], acc[fm][fn][3]);
            }
    } else {
        float* Cf = (float*)CoutV;
        #pragma unroll
        for (int fm = 0; fm < 2; fm++)
            #pragma unroll
            for (int fn = 0; fn < 8; fn++) {
                int r = m0 + wm * 32 + fm * 16 + g;
                int c = n0 + wn * 64 + fn * 8 + cpair;
                *(float2*)&Cf[(size_t)r * N + c] =
                    make_float2(acc[fm][fn][0], acc[fm][fn][1]);
                *(float2*)&Cf[(size_t)(r + 8) * N + c] =
                    make_float2(acc[fm][fn][2], acc[fm][fn][3]);
            }
    }
}

// ===========================================================================
// Flash sliding-window attention v5: fully warp-private softmax state
// (split-softmax over the warp's 32-key slice; merged once in epilogue),
// 3-deep KV prefetch. Per tile: ONE CTA sync, zero softmax smem traffic.
// ===========================================================================
#define QT 64
#define KT 64
#define NKT 5
#define OBP 72            // O exchange row pitch (floats)

#define AQ   0            // 8192
#define AK   8192         // 3 x 8192 = 24576
#define AV   32768        // 3 x 8192 = 24576
#define AOB  57344        // O exchange: 64 x OBP x 4 = 18432
#define ASR  75776        // m (64) + l (64) floats = 512
#define ATTN_SMEM_BYTES 76288

__global__ __launch_bounds__(256, 2) void attn_flash(const __half* __restrict__ qkv,
                                                     __half* __restrict__ y,
                                                     int bfix) {
    extern __shared__ char shm[];
    float* Obuf = (float*)(shm + AOB);
    float* Sm   = (float*)(shm + ASR);        // [64] m
    float* Sl   = (float*)(shm + ASR) + 64;   // [64] l

    const int tid  = threadIdx.x;
    const int lane = tid & 31;
    const int wid  = tid >> 5;
    const int wm   = wid & 3;           // row block (16 rows)
    const int wn   = wid >> 2;          // key half (32 keys)
    const int q0 = blockIdx.x * QT;
    const int h  = blockIdx.y;
    const int b  = bfix;
    const int kstart = q0 - MEMW;
    const int kt0 = (q0 < MEMW) ? (MEMW - q0) / KT : 0;

    const __half* qbase = qkv + (size_t)b * TT * QKVN + h * DD;
    const __half* kbase = qbase + CC;
    const __half* vbase = qbase + 2 * CC;

    const uint32_t uQ = smem_u32(shm) + AQ;
    const uint32_t uK = smem_u32(shm) + AK;
    const uint32_t uV = smem_u32(shm) + AV;

    const int a_row = (lane & 7) + ((lane >> 3) & 1) * 8;
    const int a_col = (lane >> 4) * 16;
    const int b_row = (lane & 7) + (lane >> 4) * 8;
    const int b_col = ((lane >> 3) & 1) * 16;
    const int g  = lane >> 2;
    const int c2 = (lane & 3) * 2;
    const int r0 = wm * 16 + g;

    #pragma unroll
    for (int it = 0; it < 2; it++) {
        int idx = it * 256 + tid;
        int row = idx >> 3;
        int cc  = idx & 7;
        cp_async16(uQ + SW128((uint32_t)(row * 128 + cc * 16)),
                   &qbase[(size_t)(q0 + row) * QKVN + cc * 8]);
    }
    auto issue_kv = [&](int kt) {
        const uint32_t boff = (uint32_t)(kt % 3) * 8192;
        const int kb = kstart + kt * KT;
        #pragma unroll
        for (int it = 0; it < 2; it++) {
            int idx = it * 256 + tid;
            int row = idx >> 3;
            int cc  = idx & 7;
            int gk  = kb + row;
            uint32_t sw = SW128((uint32_t)(row * 128 + cc * 16));
            int ok = (gk >= 0) ? 16 : 0;
            const __half* ks = (gk >= 0) ? &kbase[(size_t)gk * QKVN + cc * 8] : kbase;
            const __half* vs = (gk >= 0) ? &vbase[(size_t)gk * QKVN + cc * 8] : vbase;
            cp_async16_z(uK + boff + sw, ks, ok);
            cp_async16_z(uV + boff + sw, vs, ok);
        }
    };
    issue_kv(kt0);
    CP_COMMIT();
    if (kt0 + 1 < NKT) {
        issue_kv(kt0 + 1);
        CP_COMMIT();
    }

    float m_old0 = -1e30f, m_old1 = -1e30f;
    float srun0 = 0.f, srun1 = 0.f;
    float oacc[8][4];                   // 16 rows x 64 d (partial over keys)
    #pragma unroll
    for (int i = 0; i < 8; i++)
        #pragma unroll
        for (int j = 0; j < 4; j++) oacc[i][j] = 0.f;

    for (int kt = kt0; kt < NKT; kt++) {
        if (kt + 1 < NKT) { CP_WAIT(1); } else { CP_WAIT(0); }
        __syncthreads();               // KV(kt)+Q visible; tile kt-3 buf reusable
        if (kt + 2 < NKT) { issue_kv(kt + 2); CP_COMMIT(); }

        const int kb = kstart + kt * KT;
        const uint32_t boff = (uint32_t)(kt % 3) * 8192;

        // ---- scores: Q(16 rows) x K^T(this warp's 32 keys) ----
        float acc[4][4];
        #pragma unroll
        for (int i = 0; i < 4; i++)
            #pragma unroll
            for (int j = 0; j < 4; j++) acc[i][j] = 0.f;

        #pragma unroll
        for (int ks = 0; ks < 4; ks++) {
            uint32_t a[4];
            {
                int row = wm * 16 + a_row;
                LDSM_X4(a[0], a[1], a[2], a[3],
                        uQ + SW128((uint32_t)(row * 128 + ks * 32 + a_col)));
            }
            uint32_t bf[2][4];
            #pragma unroll
            for (int g2 = 0; g2 < 2; g2++) {
                int row = wn * 32 + g2 * 16 + b_row;
                LDSM_X4(bf[g2][0], bf[g2][1], bf[g2][2], bf[g2][3],
                        uK + boff + SW128((uint32_t)(row * 128 + ks * 32 + b_col)));
            }
            #pragma unroll
            for (int fn = 0; fn < 4; fn++) {
                const int bg = fn >> 1;
                if (fn & 1) {
                    MMA_F16(acc[fn], a[0], a[1], a[2], a[3], bf[bg][2], bf[bg][3]);
                } else {
                    MMA_F16(acc[fn], a[0], a[1], a[2], a[3], bf[bg][0], bf[bg][1]);
                }
            }
        }

        // ---- scale (+ mask only on edge tiles) + quad row max ----
        float mx0 = -1e30f, mx1 = -1e30f;
        if (kt == 0 || kt == NKT - 1) {
            const int qi0 = q0 + r0;
            const int qi1 = qi0 + 8;
            #pragma unroll
            for (int fn = 0; fn < 4; fn++) {
                int c  = wn * 32 + fn * 8 + c2;
                int kj = kb + c;
                #pragma unroll
                for (int jj = 0; jj < 2; jj++) {
                    int k = kj + jj;
                    bool ok0 = (k <= qi0) && (qi0 - k <= MEMW);
                    bool ok1 = (k <= qi1) && (qi1 - k <= MEMW);
                    acc[fn][jj]     = ok0 ? acc[fn][jj]     * SCL : -1e30f;
                    acc[fn][2 + jj] = ok1 ? acc[fn][2 + jj] * SCL : -1e30f;
                    mx0 = fmaxf(mx0, acc[fn][jj]);
                    mx1 = fmaxf(mx1, acc[fn][2 + jj]);
                }
            }
        } else {
            #pragma unroll
            for (int fn = 0; fn < 4; fn++) {
                #pragma unroll
                for (int jj = 0; jj < 2; jj++) {
                    acc[fn][jj]     *= SCL;
                    acc[fn][2 + jj] *= SCL;
                    mx0 = fmaxf(mx0, acc[fn][jj]);
                    mx1 = fmaxf(mx1, acc[fn][2 + jj]);
                }
            }
        }
        mx0 = fmaxf(mx0, __shfl_xor_sync(0xFFFFFFFF, mx0, 1));
        mx0 = fmaxf(mx0, __shfl_xor_sync(0xFFFFFFFF, mx0, 2));
        mx1 = fmaxf(mx1, __shfl_xor_sync(0xFFFFFFFF, mx1, 1));
        mx1 = fmaxf(mx1, __shfl_xor_sync(0xFFFFFFFF, mx1, 2));

        // ---- warp-private online update ----
        float m0 = fmaxf(m_old0, mx0);
        float m1 = fmaxf(m_old1, mx1);
        float f0 = ex2f(m_old0 - m0);
        float f1 = ex2f(m_old1 - m1);
        m_old0 = m0;
        m_old1 = m1;

        // ---- exp into PV A-fragments (registers) + partial sums ----
        uint32_t aP[2][4];
        float s0 = 0.f, s1 = 0.f;
        #pragma unroll
        for (int kk = 0; kk < 2; kk++) {
            float p00 = ex2f(acc[2*kk][0] - m0);
            float p01 = ex2f(acc[2*kk][1] - m0);
            float p02 = ex2f(acc[2*kk][2] - m1);
            float p03 = ex2f(acc[2*kk][3] - m1);
            float p10 = ex2f(acc[2*kk+1][0] - m0);
            float p11 = ex2f(acc[2*kk+1][1] - m0);
            float p12 = ex2f(acc[2*kk+1][2] - m1);
            float p13 = ex2f(acc[2*kk+1][3] - m1);
            aP[kk][0] = packh2(p00, p01);
            aP[kk][1] = packh2(p02, p03);
            aP[kk][2] = packh2(p10, p11);
            aP[kk][3] = packh2(p12, p13);
            s0 += p00 + p01 + p10 + p11;
            s1 += p02 + p03 + p12 + p13;
        }
        s0 += __shfl_xor_sync(0xFFFFFFFF, s0, 1);
        s0 += __shfl_xor_sync(0xFFFFFFFF, s0, 2);
        s1 += __shfl_xor_sync(0xFFFFFFFF, s1, 1);
        s1 += __shfl_xor_sync(0xFFFFFFFF, s1, 2);
        srun0 = srun0 * f0 + s0;
        srun1 = srun1 * f1 + s1;

        #pragma unroll
        for (int fn = 0; fn < 8; fn++) {
            oacc[fn][0] *= f0;
            oacc[fn][1] *= f0;
            oacc[fn][2] *= f1;
            oacc[fn][3] *= f1;
        }

        // ---- PV: O(16 x 64d) += P(16 x this warp's 32 keys) x V ----
        #pragma unroll
        for (int kk = 0; kk < 2; kk++) {
            uint32_t bf[4][4];
            #pragma unroll
            for (int g2 = 0; g2 < 4; g2++) {
                int row = wn * 32 + kk * 16 + (lane & 7) + ((lane >> 3) & 1) * 8;
                int bcol = g2 * 32 + (lane >> 4) * 16;
                LDSM_X4T(bf[g2][0], bf[g2][1], bf[g2][2], bf[g2][3],
                         uV + boff + SW128((uint32_t)(row * 128 + bcol)));
            }
            #pragma unroll
            for (int fn = 0; fn < 8; fn++) {
                const int bg = fn >> 1;
                if (fn & 1) {
                    MMA_F16(oacc[fn], aP[kk][0], aP[kk][1], aP[kk][2], aP[kk][3],
                            bf[bg][2], bf[bg][3]);
                } else {
                    MMA_F16(oacc[fn], aP[kk][0], aP[kk][1], aP[kk][2], aP[kk][3],
                            bf[bg][0], bf[bg][1]);
                }
            }
        }
    }

    // ---- epilogue: merge (O, m, l) across the warp pair, normalize, store --
    if (wn == 1) {
        #pragma unroll
        for (int fn = 0; fn < 8; fn++) {
            int col = fn * 8 + c2;
            float* d0 = &Obuf[(size_t)r0 * OBP + col];
            float* d1 = &Obuf[(size_t)(r0 + 8) * OBP + col];
            d0[0] = oacc[fn][0]; d0[1] = oacc[fn][1];
            d1[0] = oacc[fn][2]; d1[1] = oacc[fn][3];
        }
        if ((lane & 3) == 0) {
            Sm[r0] = m_old0;  Sm[r0 + 8] = m_old1;
            Sl[r0] = srun0;   Sl[r0 + 8] = srun1;
        }
    }
    BAR_PAIR(wm + 1);
    if (wn == 0) {
        float mo0 = Sm[r0], mo1 = Sm[r0 + 8];
        float lo0 = Sl[r0], lo1 = Sl[r0 + 8];
        float mm0 = fmaxf(m_old0, mo0);
        float mm1 = fmaxf(m_old1, mo1);
        float as0 = ex2f(m_old0 - mm0), ao0 = ex2f(mo0 - mm0);
        float as1 = ex2f(m_old1 - mm1), ao1 = ex2f(mo1 - mm1);
        float inv0 = 1.0f / (srun0 * as0 + lo0 * ao0);
        float inv1 = 1.0f / (srun1 * as1 + lo1 * ao1);
        #pragma unroll
        for (int fn = 0; fn < 8; fn++) {
            int col = fn * 8 + c2;
            const float* s0p = &Obuf[(size_t)r0 * OBP + col];
            const float* s1p = &Obuf[(size_t)(r0 + 8) * OBP + col];
            __half* p0 = &y[(size_t)(b * TT + q0 + r0) * CC + h * DD + col];
            __half* p1 = &y[(size_t)(b * TT + q0 + r0 + 8) * CC + h * DD + col];
            *(uint32_t*)p0 = packh2((oacc[fn][0] * as0 + s0p[0] * ao0) * inv0,
                                    (oacc[fn][1] * as0 + s0p[1] * ao0) * inv0);
            *(uint32_t*)p1 = packh2((oacc[fn][2] * as1 + s1p[0] * ao1) * inv1,
                                    (oacc[fn][3] * as1 + s1p[1] * ao1) * inv1);
        }
    }
}

// ===========================================================================
// launcher: 2-stream batch pipeline (unchanged from R13)
// ===========================================================================
extern "C" void kernel_launch(void* const* d_in, const int* in_sizes, int n_in,
                              void* d_out, int out_size) {
    const float* x      = (const float*)d_in[0];
    const float* w_attn = (const float*)d_in[1];
    const float* w_proj = (const float*)d_in[2];
    float* out = (float*)d_out;

    __half *qkv = nullptr, *yb = nullptr, *xc = nullptr, *wac = nullptr, *wpc = nullptr;
    cudaGetSymbolAddress((void**)&qkv, g_qkv);
    cudaGetSymbolAddress((void**)&yb,  g_y);
    cudaGetSymbolAddress((void**)&xc,  g_xc);
    cudaGetSymbolAddress((void**)&wac, g_wac);
    cudaGetSymbolAddress((void**)&wpc, g_wpc);

    cudaFuncSetAttribute(attn_flash,
                         cudaFuncAttributeMaxDynamicSharedMemorySize, ATTN_SMEM_BYTES);
    cudaFuncSetAttribute(gemm_fp16,
                         cudaFuncAttributeMaxDynamicSharedMemorySize, GEMM_SMEM);

    cudaStream_t s1;
    cudaStreamCreateWithFlags(&s1, cudaStreamNonBlocking);
    cudaEvent_t evQ0, evJoin;
    cudaEventCreateWithFlags(&evQ0,  cudaEventDisableTiming);
    cudaEventCreateWithFlags(&evJoin, cudaEventDisableTiming);

    const int MH = M_TOT / 2;

    {
        int total8 = (XN + WAN + WPN) / 8;
        convert_kernel<<<(total8 + 255) / 256, 256, 0, 0>>>(x, w_attn, w_proj);
    }
    {
        dim3 grid(QKVN / GBN, MH / GBM);
        gemm_fp16<<<grid, 256, GEMM_SMEM, 0>>>(xc, wac, qkv, M_TOT, QKVN, CC, 1, 0);
    }
    cudaEventRecord(evQ0, 0);
    cudaStreamWaitEvent(s1, evQ0, 0);

    {
        dim3 grid(QKVN / GBN, MH / GBM);
        gemm_fp16<<<grid, 256, GEMM_SMEM, s1>>>(xc, wac, qkv, M_TOT, QKVN, CC, 1, MH);
    }
    {
        dim3 grid(TT / QT, HH);
        attn_flash<<<grid, 256, ATTN_SMEM_BYTES, 0>>>(qkv, yb, 0);
    }
    {
        dim3 grid(CC / GBN, MH / GBM);
        gemm_fp16<<<grid, 256, GEMM_SMEM, 0>>>(yb, wpc, out, M_TOT, CC, CC, 0, 0);
    }
    {
        dim3 grid(TT / QT, HH);
        attn_flash<<<grid, 256, ATTN_SMEM_BYTES, s1>>>(qkv, yb, 1);
    }
    {
        dim3 grid(CC / GBN, MH / GBM);
        gemm_fp16<<<grid, 256, GEMM_SMEM, s1>>>(yb, wpc, out, M_TOT, CC, CC, 0, MH);
    }

    cudaEventRecord(evJoin, s1);
    cudaStreamWaitEvent(0, evJoin, 0);
}